// round 1
// baseline (speedup 1.0000x reference)
#include <cuda_runtime.h>
#include <math.h>

#define T_TOK 2048
#define H_DIM 2048
#define I_DIM 1408
#define E_NUM 8
#define CAP   2048                 // per-expert row capacity (max: every token picks this expert)
#define NSLOT (E_NUM * CAP)        // 16384
#define NPAIR (T_TOK * 2)          // 4096

// ---------------- scratch (device globals; no allocations allowed) ----------------
__device__ int   g_cnt[E_NUM];
__device__ int   g_sel[T_TOK][2];
__device__ float g_wts[T_TOK][2];
__device__ int   g_row_token[NSLOT];
__device__ int   g_row_pair[NSLOT];
__device__ float g_row_w[NSLOT];
__device__ float g_act[(size_t)NSLOT * I_DIM];      // ~92 MB
__device__ float g_pairout[(size_t)NPAIR * H_DIM];  // ~33.5 MB

// ---------------- kernel 0: reset routing counters (graph replays!) ----------------
__global__ void k_zero_counts() {
    if (threadIdx.x < E_NUM) g_cnt[threadIdx.x] = 0;
}

// ---------------- kernel 1: gating (logits -> top2 -> softmax over the two) --------
// softmax->top_k->renorm over probs == top2 of logits + 2-way softmax (monotonic map).
__global__ void k_gating(const float* __restrict__ x, const float* __restrict__ gw) {
    int t = blockIdx.x;
    const float* xr = x + (size_t)t * H_DIM;
    float acc[E_NUM];
#pragma unroll
    for (int e = 0; e < E_NUM; e++) acc[e] = 0.f;
    for (int h = threadIdx.x; h < H_DIM; h += blockDim.x) {
        float xv = xr[h];
#pragma unroll
        for (int e = 0; e < E_NUM; e++) acc[e] += xv * gw[e * H_DIM + h];
    }
#pragma unroll
    for (int e = 0; e < E_NUM; e++) {
#pragma unroll
        for (int o = 16; o > 0; o >>= 1)
            acc[e] += __shfl_down_sync(0xffffffffu, acc[e], o);
    }
    __shared__ float part[8][E_NUM];
    int wid = threadIdx.x >> 5, lane = threadIdx.x & 31;
    if (lane == 0) {
#pragma unroll
        for (int e = 0; e < E_NUM; e++) part[wid][e] = acc[e];
    }
    __syncthreads();
    if (threadIdx.x == 0) {
        float logit[E_NUM];
#pragma unroll
        for (int e = 0; e < E_NUM; e++) {
            float s = 0.f;
#pragma unroll
            for (int w = 0; w < 8; w++) s += part[w][e];
            logit[e] = s;
        }
        int e0 = 0;
#pragma unroll
        for (int e = 1; e < E_NUM; e++) if (logit[e] > logit[e0]) e0 = e;
        int e1 = (e0 == 0) ? 1 : 0;
#pragma unroll
        for (int e = 0; e < E_NUM; e++)
            if (e != e0 && logit[e] > logit[e1]) e1 = e;
        float w0 = 1.f / (1.f + expf(logit[e1] - logit[e0]));
        g_sel[t][0] = e0; g_sel[t][1] = e1;
        g_wts[t][0] = w0; g_wts[t][1] = 1.f - w0;
    }
}

// ---------------- kernel 2: build per-expert row lists -----------------------------
__global__ void k_route() {
    int t = blockIdx.x * blockDim.x + threadIdx.x;
    if (t >= T_TOK) return;
#pragma unroll
    for (int k = 0; k < 2; k++) {
        int e = g_sel[t][k];
        int pos = atomicAdd(&g_cnt[e], 1);
        int r = e * CAP + pos;
        g_row_token[r] = t;
        g_row_pair[r]  = t * 2 + k;
        g_row_w[r]     = g_wts[t][k];
    }
}

// ---------------- kernel 3: GEMM1 fused gate/up + SiLU -----------------------------
// act[r, n] = silu(x[tok(r)] . w1[e, n, :]) * (x[tok(r)] . w1[e, I+n, :])
// Tile: 128(M) x 64(N over I) x 16(K over H); 256 threads; 8x4 per thread, dual acc.
__global__ void __launch_bounds__(256) k_gemm1(const float* __restrict__ x,
                                               const float* __restrict__ w1) {
    const int e   = blockIdx.z;
    const int cnt = g_cnt[e];
    const int m0  = blockIdx.y * 128;
    if (m0 >= cnt) return;
    const int n0  = blockIdx.x * 64;

    __shared__ float As[16][132];
    __shared__ float Bg[16][68];
    __shared__ float Bu[16][68];

    const int tid = threadIdx.x;
    const int tx = tid & 15, ty = tid >> 4;

    int arow[2], acol[2], atok[2];
#pragma unroll
    for (int it = 0; it < 2; it++) {
        int j = tid + 256 * it;
        arow[it] = j >> 2;
        acol[it] = (j & 3) * 4;
        int gm = m0 + arow[it];
        atok[it] = (gm < cnt) ? g_row_token[e * CAP + gm] : -1;
    }
    const int brow = tid >> 2;
    const int bcol = (tid & 3) * 4;
    const float* w1g = w1 + ((size_t)e * 2 * I_DIM + n0) * H_DIM;
    const float* w1u = w1g + (size_t)I_DIM * H_DIM;

    float accg[8][4], accu[8][4];
#pragma unroll
    for (int m = 0; m < 8; m++)
#pragma unroll
        for (int n = 0; n < 4; n++) { accg[m][n] = 0.f; accu[m][n] = 0.f; }

    for (int kk = 0; kk < H_DIM; kk += 16) {
#pragma unroll
        for (int it = 0; it < 2; it++) {
            float4 v = make_float4(0.f, 0.f, 0.f, 0.f);
            if (atok[it] >= 0)
                v = *(const float4*)(x + (size_t)atok[it] * H_DIM + kk + acol[it]);
            As[acol[it] + 0][arow[it]] = v.x;
            As[acol[it] + 1][arow[it]] = v.y;
            As[acol[it] + 2][arow[it]] = v.z;
            As[acol[it] + 3][arow[it]] = v.w;
        }
        {
            float4 vg = *(const float4*)(w1g + (size_t)brow * H_DIM + kk + bcol);
            float4 vu = *(const float4*)(w1u + (size_t)brow * H_DIM + kk + bcol);
            Bg[bcol + 0][brow] = vg.x; Bg[bcol + 1][brow] = vg.y;
            Bg[bcol + 2][brow] = vg.z; Bg[bcol + 3][brow] = vg.w;
            Bu[bcol + 0][brow] = vu.x; Bu[bcol + 1][brow] = vu.y;
            Bu[bcol + 2][brow] = vu.z; Bu[bcol + 3][brow] = vu.w;
        }
        __syncthreads();
#pragma unroll
        for (int k = 0; k < 16; k++) {
            float4 a0 = *(const float4*)&As[k][ty * 8];
            float4 a1 = *(const float4*)&As[k][ty * 8 + 4];
            float4 bg = *(const float4*)&Bg[k][tx * 4];
            float4 bu = *(const float4*)&Bu[k][tx * 4];
            float a[8]   = {a0.x, a0.y, a0.z, a0.w, a1.x, a1.y, a1.z, a1.w};
            float bgv[4] = {bg.x, bg.y, bg.z, bg.w};
            float buv[4] = {bu.x, bu.y, bu.z, bu.w};
#pragma unroll
            for (int m = 0; m < 8; m++)
#pragma unroll
                for (int n = 0; n < 4; n++) {
                    accg[m][n] += a[m] * bgv[n];
                    accu[m][n] += a[m] * buv[n];
                }
        }
        __syncthreads();
    }

#pragma unroll
    for (int m = 0; m < 8; m++) {
        int gm = m0 + ty * 8 + m;
        if (gm >= cnt) continue;
        size_t base = (size_t)(e * CAP + gm) * I_DIM + n0 + tx * 4;
#pragma unroll
        for (int n = 0; n < 4; n++) {
            float g = accg[m][n], u = accu[m][n];
            float s = g / (1.f + expf(-g));   // silu(g)
            g_act[base + n] = s * u;
        }
    }
}

// ---------------- kernel 4: GEMM2 down-proj, routing weight folded in --------------
// pairout[pair(r), h] = w(r) * (act[r, :] . w2[e, h, :])
// Tile: 128(M) x 128(N over H) x 16(K over I); 256 threads; 8x8 per thread.
__global__ void __launch_bounds__(256) k_gemm2(const float* __restrict__ w2) {
    const int e   = blockIdx.z;
    const int cnt = g_cnt[e];
    const int m0  = blockIdx.y * 128;
    if (m0 >= cnt) return;
    const int n0  = blockIdx.x * 128;

    __shared__ float As[16][132];
    __shared__ float Bs[16][132];

    const int tid = threadIdx.x;
    const int tx = tid & 15, ty = tid >> 4;

    int lrow[2], lcol[2];
    bool avalid[2];
#pragma unroll
    for (int it = 0; it < 2; it++) {
        int j = tid + 256 * it;
        lrow[it] = j >> 2;
        lcol[it] = (j & 3) * 4;
        avalid[it] = (m0 + lrow[it]) < cnt;
    }
    const float* bptr = w2 + ((size_t)e * H_DIM + n0) * I_DIM;
    const float* aptr = g_act + (size_t)(e * CAP + m0) * I_DIM;

    float acc[8][8];
#pragma unroll
    for (int m = 0; m < 8; m++)
#pragma unroll
        for (int n = 0; n < 8; n++) acc[m][n] = 0.f;

    for (int kk = 0; kk < I_DIM; kk += 16) {
#pragma unroll
        for (int it = 0; it < 2; it++) {
            float4 v = make_float4(0.f, 0.f, 0.f, 0.f);
            if (avalid[it])
                v = *(const float4*)(aptr + (size_t)lrow[it] * I_DIM + kk + lcol[it]);
            As[lcol[it] + 0][lrow[it]] = v.x;
            As[lcol[it] + 1][lrow[it]] = v.y;
            As[lcol[it] + 2][lrow[it]] = v.z;
            As[lcol[it] + 3][lrow[it]] = v.w;
            float4 b = *(const float4*)(bptr + (size_t)lrow[it] * I_DIM + kk + lcol[it]);
            Bs[lcol[it] + 0][lrow[it]] = b.x;
            Bs[lcol[it] + 1][lrow[it]] = b.y;
            Bs[lcol[it] + 2][lrow[it]] = b.z;
            Bs[lcol[it] + 3][lrow[it]] = b.w;
        }
        __syncthreads();
#pragma unroll
        for (int k = 0; k < 16; k++) {
            float4 a0 = *(const float4*)&As[k][ty * 8];
            float4 a1 = *(const float4*)&As[k][ty * 8 + 4];
            float4 b0 = *(const float4*)&Bs[k][tx * 8];
            float4 b1 = *(const float4*)&Bs[k][tx * 8 + 4];
            float a[8] = {a0.x, a0.y, a0.z, a0.w, a1.x, a1.y, a1.z, a1.w};
            float b[8] = {b0.x, b0.y, b0.z, b0.w, b1.x, b1.y, b1.z, b1.w};
#pragma unroll
            for (int m = 0; m < 8; m++)
#pragma unroll
                for (int n = 0; n < 8; n++) acc[m][n] += a[m] * b[n];
        }
        __syncthreads();
    }

#pragma unroll
    for (int m = 0; m < 8; m++) {
        int gm = m0 + ty * 8 + m;
        if (gm >= cnt) continue;
        int r = e * CAP + gm;
        int p = g_row_pair[r];
        float w = g_row_w[r];
        float* o = g_pairout + (size_t)p * H_DIM + n0 + tx * 8;
#pragma unroll
        for (int n = 0; n < 8; n++) o[n] = w * acc[m][n];
    }
}

// ---------------- kernel 5: deterministic combine (2 pairs per token) --------------
__global__ void k_combine(float* __restrict__ out) {
    int i = blockIdx.x * blockDim.x + threadIdx.x;   // float4 index, total T*H/4
    int t = i / (H_DIM / 4);
    int c = i % (H_DIM / 4);
    const float4* p0 = (const float4*)(g_pairout + (size_t)(2 * t) * H_DIM) + c;
    const float4* p1 = (const float4*)(g_pairout + (size_t)(2 * t + 1) * H_DIM) + c;
    float4 a = *p0, b = *p1;
    float4 r = make_float4(a.x + b.x, a.y + b.y, a.z + b.z, a.w + b.w);
    ((float4*)out)[i] = r;
}

// ---------------- launch ------------------------------------------------------------
extern "C" void kernel_launch(void* const* d_in, const int* in_sizes, int n_in,
                              void* d_out, int out_size) {
    const float* x  = (const float*)d_in[0];   // hidden_states [2,1024,2048]
    const float* gw = (const float*)d_in[1];   // gate_w [8,2048]
    const float* w1 = (const float*)d_in[2];   // [8,2816,2048]
    const float* w2 = (const float*)d_in[3];   // [8,2048,1408]
    float* out = (float*)d_out;                // [2,1024,2048] f32

    k_zero_counts<<<1, 32>>>();
    k_gating<<<T_TOK, 256>>>(x, gw);
    k_route<<<(T_TOK + 255) / 256, 256>>>();

    dim3 g1(I_DIM / 64, CAP / 128, E_NUM);     // (22,16,8), early-exit on count
    k_gemm1<<<g1, 256>>>(x, w1);

    dim3 g2(H_DIM / 128, CAP / 128, E_NUM);    // (16,16,8)
    k_gemm2<<<g2, 256>>>(w2);

    k_combine<<<(T_TOK * H_DIM / 4) / 256, 256>>>(out);
}

// round 4
// speedup vs baseline: 1.3576x; 1.3576x over previous
#include <cuda_runtime.h>
#include <cuda_bf16.h>
#include <math.h>
#include <stdint.h>

#define T_TOK 2048
#define H_DIM 2048
#define I_DIM 1408
#define E_NUM 8
#define CAP   2048
#define NSLOT (E_NUM * CAP)
#define AW    34            // smem row stride in words for a 32-float row (pad 2)

// ---------------- scratch ----------------
__device__ int   g_cnt[E_NUM];
__device__ int   g_sel[T_TOK][2];
__device__ float g_wts[T_TOK][2];
__device__ int   g_row_token[NSLOT];
__device__ float g_row_w[NSLOT];
__device__ float g_act[(size_t)NSLOT * I_DIM];

// ---------------- helpers ----------------
__device__ __forceinline__ uint32_t smem_u32(const void* p) {
    uint32_t a;
    asm("{ .reg .u64 t; cvta.to.shared.u64 t, %1; cvt.u32.u64 %0, t; }" : "=r"(a) : "l"(p));
    return a;
}
#define CP8(dst, src, sz) \
    asm volatile("cp.async.ca.shared.global [%0], [%1], 8, %2;" :: "r"(dst), "l"(src), "r"(sz) : "memory")
#define CP_COMMIT() asm volatile("cp.async.commit_group;" ::: "memory")
#define CP_WAIT2()  asm volatile("cp.async.wait_group 2;" ::: "memory")

// fp32 pair -> bf16 hi pair + bf16 lo pair (packed b32 each)
__device__ __forceinline__ void cvt2(float2 v, uint32_t& h, uint32_t& l) {
    __nv_bfloat162 hb = __float22bfloat162_rn(v);
    float2 hf = __bfloat1622float2(hb);
    __nv_bfloat162 lb = __float22bfloat162_rn(make_float2(v.x - hf.x, v.y - hf.y));
    h = *(uint32_t*)&hb;
    l = *(uint32_t*)&lb;
}

__device__ __forceinline__ void mma16816(float* c, uint32_t a0, uint32_t a1, uint32_t a2, uint32_t a3,
                                         uint32_t b0, uint32_t b1) {
    asm volatile(
        "mma.sync.aligned.m16n8k16.row.col.f32.bf16.bf16.f32 "
        "{%0,%1,%2,%3}, {%4,%5,%6,%7}, {%8,%9}, {%0,%1,%2,%3};"
        : "+f"(c[0]), "+f"(c[1]), "+f"(c[2]), "+f"(c[3])
        : "r"(a0), "r"(a1), "r"(a2), "r"(a3), "r"(b0), "r"(b1));
}
// full-precision product via 3 bf16 mmas: hi*hi + hi*lo + lo*hi
__device__ __forceinline__ void mma3(float* c, const uint32_t* ah, const uint32_t* al,
                                     const uint32_t* bh, const uint32_t* bl) {
    mma16816(c, ah[0], ah[1], ah[2], ah[3], bh[0], bh[1]);
    mma16816(c, ah[0], ah[1], ah[2], ah[3], bl[0], bl[1]);
    mma16816(c, al[0], al[1], al[2], al[3], bh[0], bh[1]);
}

// A fragment: 16(m) x 16(k) row-major tile at (rbase, kw) of smem [rows][AW]
__device__ __forceinline__ void load_afrag(const float* As, int rbase, int kw, int g, int t4,
                                           uint32_t* h, uint32_t* l) {
    int c0 = kw + 2 * t4;
    float2 v0 = *(const float2*)(As + (size_t)(rbase + g) * AW + c0);
    float2 v1 = *(const float2*)(As + (size_t)(rbase + g + 8) * AW + c0);
    float2 v2 = *(const float2*)(As + (size_t)(rbase + g) * AW + c0 + 8);
    float2 v3 = *(const float2*)(As + (size_t)(rbase + g + 8) * AW + c0 + 8);
    cvt2(v0, h[0], l[0]); cvt2(v1, h[1], l[1]); cvt2(v2, h[2], l[2]); cvt2(v3, h[3], l[3]);
}
// B fragment: 8(n) x 16(k), B stored [n][k] row-major (k-major => "col" operand)
__device__ __forceinline__ void load_bfrag(const float* Bs, int nbase, int kw, int g, int t4,
                                           uint32_t* h, uint32_t* l) {
    int c0 = kw + 2 * t4;
    float2 v0 = *(const float2*)(Bs + (size_t)(nbase + g) * AW + c0);
    float2 v1 = *(const float2*)(Bs + (size_t)(nbase + g) * AW + c0 + 8);
    cvt2(v0, h[0], l[0]); cvt2(v1, h[1], l[1]);
}

// ---------------- gating / routing (proven in R1) ----------------
__global__ void k_zero_counts() { if (threadIdx.x < E_NUM) g_cnt[threadIdx.x] = 0; }

__global__ void k_gating(const float* __restrict__ x, const float* __restrict__ gw) {
    int t = blockIdx.x;
    const float* xr = x + (size_t)t * H_DIM;
    float acc[E_NUM];
#pragma unroll
    for (int e = 0; e < E_NUM; e++) acc[e] = 0.f;
    for (int h = threadIdx.x; h < H_DIM; h += blockDim.x) {
        float xv = xr[h];
#pragma unroll
        for (int e = 0; e < E_NUM; e++) acc[e] += xv * gw[e * H_DIM + h];
    }
#pragma unroll
    for (int e = 0; e < E_NUM; e++)
#pragma unroll
        for (int o = 16; o > 0; o >>= 1) acc[e] += __shfl_down_sync(0xffffffffu, acc[e], o);
    __shared__ float part[8][E_NUM];
    int wid = threadIdx.x >> 5, lane = threadIdx.x & 31;
    if (lane == 0)
#pragma unroll
        for (int e = 0; e < E_NUM; e++) part[wid][e] = acc[e];
    __syncthreads();
    if (threadIdx.x == 0) {
        float logit[E_NUM];
#pragma unroll
        for (int e = 0; e < E_NUM; e++) {
            float s = 0.f;
#pragma unroll
            for (int w = 0; w < 8; w++) s += part[w][e];
            logit[e] = s;
        }
        int e0 = 0;
#pragma unroll
        for (int e = 1; e < E_NUM; e++) if (logit[e] > logit[e0]) e0 = e;
        int e1 = (e0 == 0) ? 1 : 0;
#pragma unroll
        for (int e = 0; e < E_NUM; e++) if (e != e0 && logit[e] > logit[e1]) e1 = e;
        float w0 = 1.f / (1.f + expf(logit[e1] - logit[e0]));
        g_sel[t][0] = e0; g_sel[t][1] = e1;
        g_wts[t][0] = w0; g_wts[t][1] = 1.f - w0;
    }
}

__global__ void k_route() {
    int t = blockIdx.x * blockDim.x + threadIdx.x;
    if (t >= T_TOK) return;
#pragma unroll
    for (int k = 0; k < 2; k++) {
        int e = g_sel[t][k];
        int pos = atomicAdd(&g_cnt[e], 1);
        g_row_token[e * CAP + pos] = t;
        g_row_w[e * CAP + pos] = g_wts[t][k];
    }
}

__global__ void k_zero_out(float* __restrict__ out) {
    int i = blockIdx.x * blockDim.x + threadIdx.x;
    ((float4*)out)[i] = make_float4(0.f, 0.f, 0.f, 0.f);
}

// ================= GEMM1: x[rows] @ w1^T, gate+up fused, SiLU epilogue =================
// CTA tile: M=128 (gathered rows), N=64 (gate) + 64 (up), BK=32. 8 warps (4m x 2n).
#define G1_STAGE_W (128 * AW + 64 * AW + 64 * AW)   // 8704 words
#define G1_SMEM    (3 * G1_STAGE_W * 4)

__global__ void __launch_bounds__(256, 1) k_gemm1(const float* __restrict__ x,
                                                  const float* __restrict__ w1) {
    const int e = blockIdx.z;
    const int cnt = g_cnt[e];
    const int m0 = blockIdx.x * 128;
    if (m0 >= cnt) return;
    const int n0 = blockIdx.y * 64;

    extern __shared__ float sm[];
    const uint32_t sb = smem_u32(sm);
    const int tid = threadIdx.x, lane = tid & 31, wid = tid >> 5;
    const int g = lane >> 2, t4 = lane & 3;
    const int wm = wid >> 1, wn = wid & 1;

    // per-thread cp.async geometry: cc = tid&15 (chunk within row), row = tid>>4 + 16*j
    const int cc = tid & 15, r0 = tid >> 4;
    const float* a_src[8];
    uint32_t a_mask = 0;
#pragma unroll
    for (int j = 0; j < 8; j++) {
        int gm = m0 + r0 + 16 * j;
        int ok = gm < cnt;
        int tok = ok ? g_row_token[e * CAP + gm] : 0;
        a_src[j] = x + (size_t)tok * H_DIM + cc * 2;
        a_mask |= (ok ? 1u : 0u) << j;
    }
    const float* bg_base = w1 + ((size_t)e * 2 * I_DIM + n0 + r0) * H_DIM + cc * 2;
    const float* bu_base = bg_base + (size_t)I_DIM * H_DIM;
    const uint32_t dstw0 = (uint32_t)(r0 * AW + cc * 2) * 4;   // bytes

    float accg[2][4][4], accu[2][4][4];
#pragma unroll
    for (int mt = 0; mt < 2; mt++)
#pragma unroll
        for (int nt = 0; nt < 4; nt++)
#pragma unroll
            for (int i = 0; i < 4; i++) { accg[mt][nt][i] = 0.f; accu[mt][nt][i] = 0.f; }

    const int NC = H_DIM / 32;   // 64

#define G1_ISSUE(c) do { \
    int _s = (c) % 3; \
    uint32_t _ab = sb + (uint32_t)(_s * G1_STAGE_W) * 4; \
    uint32_t _gb = _ab + 128 * AW * 4; \
    uint32_t _ub = _gb + 64 * AW * 4; \
    int _ko = (c) * 32; \
    _Pragma("unroll") \
    for (int _j = 0; _j < 8; _j++) { \
        int _sz = ((a_mask >> _j) & 1) ? 8 : 0; \
        CP8(_ab + dstw0 + (uint32_t)(_j * 16 * AW * 4), a_src[_j] + _ko, _sz); \
    } \
    _Pragma("unroll") \
    for (int _j = 0; _j < 4; _j++) { \
        CP8(_gb + dstw0 + (uint32_t)(_j * 16 * AW * 4), bg_base + (size_t)(_j * 16) * H_DIM + _ko, 8); \
        CP8(_ub + dstw0 + (uint32_t)(_j * 16 * AW * 4), bu_base + (size_t)(_j * 16) * H_DIM + _ko, 8); \
    } \
} while (0)

    G1_ISSUE(0); CP_COMMIT();
    G1_ISSUE(1); CP_COMMIT();

    for (int c = 0; c < NC; c++) {
        if (c + 2 < NC) { G1_ISSUE(c + 2); }
        CP_COMMIT();
        CP_WAIT2();
        __syncthreads();
        const float* As = sm + (size_t)(c % 3) * G1_STAGE_W;
        const float* Bg = As + 128 * AW;
        const float* Bu = Bg + 64 * AW;
#pragma unroll
        for (int ks = 0; ks < 2; ks++) {
            const int kw = ks * 16;
            uint32_t ah[2][4], al[2][4];
#pragma unroll
            for (int mt = 0; mt < 2; mt++)
                load_afrag(As, wm * 32 + mt * 16, kw, g, t4, ah[mt], al[mt]);
            uint32_t gh[4][2], gl[4][2], uh[4][2], ul[4][2];
#pragma unroll
            for (int nt = 0; nt < 4; nt++) {
                load_bfrag(Bg, wn * 32 + nt * 8, kw, g, t4, gh[nt], gl[nt]);
                load_bfrag(Bu, wn * 32 + nt * 8, kw, g, t4, uh[nt], ul[nt]);
            }
#pragma unroll
            for (int mt = 0; mt < 2; mt++)
#pragma unroll
                for (int nt = 0; nt < 4; nt++) {
                    mma3(accg[mt][nt], ah[mt], al[mt], gh[nt], gl[nt]);
                    mma3(accu[mt][nt], ah[mt], al[mt], uh[nt], ul[nt]);
                }
        }
        __syncthreads();
    }

    // epilogue: act = silu(gate) * up
    const int melim = cnt - m0;
#pragma unroll
    for (int mt = 0; mt < 2; mt++) {
#pragma unroll
        for (int half = 0; half < 2; half++) {
            int r = wm * 32 + mt * 16 + g + half * 8;
            if (r < melim) {
                float* rowp = g_act + (size_t)(e * CAP + m0 + r) * I_DIM + n0 + wn * 32 + 2 * t4;
#pragma unroll
                for (int nt = 0; nt < 4; nt++) {
                    float g0 = accg[mt][nt][half * 2 + 0], g1 = accg[mt][nt][half * 2 + 1];
                    float u0 = accu[mt][nt][half * 2 + 0], u1 = accu[mt][nt][half * 2 + 1];
                    float2 o;
                    o.x = u0 * (g0 / (1.f + expf(-g0)));
                    o.y = u1 * (g1 / (1.f + expf(-g1)));
                    *(float2*)(rowp + nt * 8) = o;
                }
            }
        }
    }
}

// ================= GEMM2: act @ w2^T, routing weight + deterministic atomic combine ===
// CTA tile: M=128, N=128, BK=32. 8 warps (2m x 4n), warp patch 64x32.
#define G2_STAGE_W (128 * AW + 128 * AW)   // 8704 words
#define G2_SMEM    (3 * G2_STAGE_W * 4)

__global__ void __launch_bounds__(256, 1) k_gemm2(const float* __restrict__ w2,
                                                  float* __restrict__ out) {
    const int e = blockIdx.z;
    const int cnt = g_cnt[e];
    const int m0 = blockIdx.x * 128;
    if (m0 >= cnt) return;
    const int n0 = blockIdx.y * 128;

    extern __shared__ float sm[];
    const uint32_t sb = smem_u32(sm);
    const int tid = threadIdx.x, lane = tid & 31, wid = tid >> 5;
    const int g = lane >> 2, t4 = lane & 3;
    const int wm = wid >> 2, wn = wid & 3;

    const int cc = tid & 15, r0 = tid >> 4;
    uint32_t a_mask = 0;
#pragma unroll
    for (int j = 0; j < 8; j++)
        if (m0 + r0 + 16 * j < cnt) a_mask |= 1u << j;
    const float* a_base = g_act + (size_t)(e * CAP + m0 + r0) * I_DIM + cc * 2;
    const float* b_base = w2 + ((size_t)e * H_DIM + n0 + r0) * I_DIM + cc * 2;
    const uint32_t dstw0 = (uint32_t)(r0 * AW + cc * 2) * 4;

    float acc[4][4][4];
#pragma unroll
    for (int mt = 0; mt < 4; mt++)
#pragma unroll
        for (int nt = 0; nt < 4; nt++)
#pragma unroll
            for (int i = 0; i < 4; i++) acc[mt][nt][i] = 0.f;

    const int NC = I_DIM / 32;   // 44

#define G2_ISSUE(c) do { \
    int _s = (c) % 3; \
    uint32_t _ab = sb + (uint32_t)(_s * G2_STAGE_W) * 4; \
    uint32_t _bb = _ab + 128 * AW * 4; \
    int _ko = (c) * 32; \
    _Pragma("unroll") \
    for (int _j = 0; _j < 8; _j++) { \
        int _sz = ((a_mask >> _j) & 1) ? 8 : 0; \
        CP8(_ab + dstw0 + (uint32_t)(_j * 16 * AW * 4), a_base + (size_t)(_j * 16) * I_DIM + _ko, _sz); \
        CP8(_bb + dstw0 + (uint32_t)(_j * 16 * AW * 4), b_base + (size_t)(_j * 16) * I_DIM + _ko, 8); \
    } \
} while (0)

    G2_ISSUE(0); CP_COMMIT();
    G2_ISSUE(1); CP_COMMIT();

    for (int c = 0; c < NC; c++) {
        if (c + 2 < NC) { G2_ISSUE(c + 2); }
        CP_COMMIT();
        CP_WAIT2();
        __syncthreads();
        const float* As = sm + (size_t)(c % 3) * G2_STAGE_W;
        const float* Bs = As + 128 * AW;
#pragma unroll
        for (int ks = 0; ks < 2; ks++) {
            const int kw = ks * 16;
            uint32_t ah[4][4], al[4][4];
#pragma unroll
            for (int mt = 0; mt < 4; mt++)
                load_afrag(As, wm * 64 + mt * 16, kw, g, t4, ah[mt], al[mt]);
            uint32_t bh[4][2], bl[4][2];
#pragma unroll
            for (int nt = 0; nt < 4; nt++)
                load_bfrag(Bs, wn * 32 + nt * 8, kw, g, t4, bh[nt], bl[nt]);
#pragma unroll
            for (int mt = 0; mt < 4; mt++)
#pragma unroll
                for (int nt = 0; nt < 4; nt++)
                    mma3(acc[mt][nt], ah[mt], al[mt], bh[nt], bl[nt]);
        }
        __syncthreads();
    }

    // epilogue: out[tok] += w * acc (exactly 2 commutative adds per element -> deterministic)
    const int melim = cnt - m0;
#pragma unroll
    for (int mt = 0; mt < 4; mt++) {
#pragma unroll
        for (int half = 0; half < 2; half++) {
            int r = wm * 64 + mt * 16 + g + half * 8;
            if (r < melim) {
                int slot = e * CAP + m0 + r;
                int tok = g_row_token[slot];
                float w = g_row_w[slot];
                float* orow = out + (size_t)tok * H_DIM + n0 + wn * 32 + 2 * t4;
#pragma unroll
                for (int nt = 0; nt < 4; nt++) {
                    atomicAdd(orow + nt * 8 + 0, w * acc[mt][nt][half * 2 + 0]);
                    atomicAdd(orow + nt * 8 + 1, w * acc[mt][nt][half * 2 + 1]);
                }
            }
        }
    }
}

// ---------------- launch ----------------
extern "C" void kernel_launch(void* const* d_in, const int* in_sizes, int n_in,
                              void* d_out, int out_size) {
    const float* x  = (const float*)d_in[0];
    const float* gw = (const float*)d_in[1];
    const float* w1 = (const float*)d_in[2];
    const float* w2 = (const float*)d_in[3];
    float* out = (float*)d_out;

    cudaFuncSetAttribute(k_gemm1, cudaFuncAttributeMaxDynamicSharedMemorySize, G1_SMEM);
    cudaFuncSetAttribute(k_gemm2, cudaFuncAttributeMaxDynamicSharedMemorySize, G2_SMEM);

    k_zero_counts<<<1, 32>>>();
    k_gating<<<T_TOK, 256>>>(x, gw);
    k_route<<<(T_TOK + 255) / 256, 256>>>();
    k_zero_out<<<(T_TOK * H_DIM / 4) / 256, 256>>>(out);

    dim3 g1(CAP / 128, I_DIM / 64, E_NUM);    // (16, 22, 8): m fastest for weight L2 reuse
    k_gemm1<<<g1, 256, G1_SMEM>>>(x, w1);

    dim3 g2(CAP / 128, H_DIM / 128, E_NUM);   // (16, 16, 8)
    k_gemm2<<<g2, 256, G2_SMEM>>>(w2, out);
}

// round 7
// speedup vs baseline: 1.8976x; 1.3978x over previous
#include <cuda_runtime.h>
#include <cuda_bf16.h>
#include <math.h>
#include <stdint.h>

#define T_TOK 2048
#define H_DIM 2048
#define I_DIM 1408
#define E_NUM 8
#define CAP   2048
#define NSLOT (E_NUM * CAP)
#define SROW  80           // smem row stride in bytes (32 bf16 = 64B data + 16B pad)

// ---------------- scratch ----------------
__device__ int   g_cnt[E_NUM];
__device__ int   g_sel[T_TOK][2];
__device__ float g_wts[T_TOK][2];
__device__ int   g_row_token[NSLOT];
__device__ float g_row_w[NSLOT];
// bf16 hi/lo shadows
__device__ __nv_bfloat16 g_xh[(size_t)T_TOK * H_DIM];
__device__ __nv_bfloat16 g_xl[(size_t)T_TOK * H_DIM];
__device__ __nv_bfloat16 g_w1h[(size_t)E_NUM * 2 * I_DIM * H_DIM];
__device__ __nv_bfloat16 g_w1l[(size_t)E_NUM * 2 * I_DIM * H_DIM];
__device__ __nv_bfloat16 g_w2h[(size_t)E_NUM * H_DIM * I_DIM];
__device__ __nv_bfloat16 g_w2l[(size_t)E_NUM * H_DIM * I_DIM];
__device__ __nv_bfloat16 g_acth[(size_t)NSLOT * I_DIM];
__device__ __nv_bfloat16 g_actl[(size_t)NSLOT * I_DIM];

// ---------------- helpers ----------------
__device__ __forceinline__ uint32_t smem_u32(const void* p) {
    uint32_t a;
    asm("{ .reg .u64 t; cvta.to.shared.u64 t, %1; cvt.u32.u64 %0, t; }" : "=r"(a) : "l"(p));
    return a;
}
#define CP16(dst, src, sz) \
    asm volatile("cp.async.cg.shared.global [%0], [%1], 16, %2;" :: "r"(dst), "l"(src), "r"(sz) : "memory")
#define CP_COMMIT() asm volatile("cp.async.commit_group;" ::: "memory")
#define CP_WAIT2()  asm volatile("cp.async.wait_group 2;" ::: "memory")

__device__ __forceinline__ void ldsm_x4(uint32_t* r, uint32_t addr) {
    asm volatile("ldmatrix.sync.aligned.m8n8.x4.shared.b16 {%0,%1,%2,%3}, [%4];"
        : "=r"(r[0]), "=r"(r[1]), "=r"(r[2]), "=r"(r[3]) : "r"(addr));
}
__device__ __forceinline__ void cvt2(float2 v, uint32_t& h, uint32_t& l) {
    __nv_bfloat162 hb = __float22bfloat162_rn(v);
    float2 hf = __bfloat1622float2(hb);
    __nv_bfloat162 lb = __float22bfloat162_rn(make_float2(v.x - hf.x, v.y - hf.y));
    h = *(uint32_t*)&hb;
    l = *(uint32_t*)&lb;
}
__device__ __forceinline__ void mma16816(float* c, const uint32_t* a, const uint32_t* b) {
    asm volatile(
        "mma.sync.aligned.m16n8k16.row.col.f32.bf16.bf16.f32 "
        "{%0,%1,%2,%3}, {%4,%5,%6,%7}, {%8,%9}, {%0,%1,%2,%3};"
        : "+f"(c[0]), "+f"(c[1]), "+f"(c[2]), "+f"(c[3])
        : "r"(a[0]), "r"(a[1]), "r"(a[2]), "r"(a[3]), "r"(b[0]), "r"(b[1]));
}
__device__ __forceinline__ void mma3(float* c, const uint32_t* ah, const uint32_t* al,
                                     const uint32_t* bh, const uint32_t* bl) {
    mma16816(c, ah, bh);
    mma16816(c, ah, bl);
    mma16816(c, al, bh);
}

// ---------------- conversion: fp32 -> bf16 hi/lo ----------------
__global__ void k_cvt(const float4* __restrict__ src, uint2* __restrict__ hi,
                      uint2* __restrict__ lo, int n4) {
    int i = blockIdx.x * blockDim.x + threadIdx.x;
    if (i >= n4) return;
    float4 v = src[i];
    uint32_t h0, l0, h1, l1;
    cvt2(make_float2(v.x, v.y), h0, l0);
    cvt2(make_float2(v.z, v.w), h1, l1);
    hi[i] = make_uint2(h0, h1);
    lo[i] = make_uint2(l0, l1);
}

// ---------------- gating / routing (proven) ----------------
__global__ void k_zero_counts() { if (threadIdx.x < E_NUM) g_cnt[threadIdx.x] = 0; }

__global__ void k_gating(const float* __restrict__ x, const float* __restrict__ gw) {
    int t = blockIdx.x;
    const float* xr = x + (size_t)t * H_DIM;
    float acc[E_NUM];
#pragma unroll
    for (int e = 0; e < E_NUM; e++) acc[e] = 0.f;
    for (int h = threadIdx.x; h < H_DIM; h += blockDim.x) {
        float xv = xr[h];
#pragma unroll
        for (int e = 0; e < E_NUM; e++) acc[e] += xv * gw[e * H_DIM + h];
    }
#pragma unroll
    for (int e = 0; e < E_NUM; e++)
#pragma unroll
        for (int o = 16; o > 0; o >>= 1) acc[e] += __shfl_down_sync(0xffffffffu, acc[e], o);
    __shared__ float part[8][E_NUM];
    int wid = threadIdx.x >> 5, lane = threadIdx.x & 31;
    if (lane == 0)
#pragma unroll
        for (int e = 0; e < E_NUM; e++) part[wid][e] = acc[e];
    __syncthreads();
    if (threadIdx.x == 0) {
        float logit[E_NUM];
#pragma unroll
        for (int e = 0; e < E_NUM; e++) {
            float s = 0.f;
#pragma unroll
            for (int w = 0; w < 8; w++) s += part[w][e];
            logit[e] = s;
        }
        int e0 = 0;
#pragma unroll
        for (int e = 1; e < E_NUM; e++) if (logit[e] > logit[e0]) e0 = e;
        int e1 = (e0 == 0) ? 1 : 0;
#pragma unroll
        for (int e = 0; e < E_NUM; e++) if (e != e0 && logit[e] > logit[e1]) e1 = e;
        float w0 = 1.f / (1.f + expf(logit[e1] - logit[e0]));
        g_sel[t][0] = e0; g_sel[t][1] = e1;
        g_wts[t][0] = w0; g_wts[t][1] = 1.f - w0;
    }
}

__global__ void k_route() {
    int t = blockIdx.x * blockDim.x + threadIdx.x;
    if (t >= T_TOK) return;
#pragma unroll
    for (int k = 0; k < 2; k++) {
        int e = g_sel[t][k];
        int pos = atomicAdd(&g_cnt[e], 1);
        g_row_token[e * CAP + pos] = t;
        g_row_w[e * CAP + pos] = g_wts[t][k];
    }
}

__global__ void k_zero_out(float* __restrict__ out) {
    int i = blockIdx.x * blockDim.x + threadIdx.x;
    ((float4*)out)[i] = make_float4(0.f, 0.f, 0.f, 0.f);
}

// ================= GEMM1: M=128 (gathered) x N=64(gate)+64(up), BK=32 =================
// Stage layout (bytes): Ah 0, Al 10240, Bgh 20480, Bgl 25600, Buh 30720, Bul 35840.
#define G1_STG  40960
#define G1_SMEM (3 * G1_STG)

__global__ void __launch_bounds__(256, 1) k_gemm1() {
    const int e = blockIdx.z;
    const int cnt = g_cnt[e];
    const int m0 = blockIdx.x * 128;
    if (m0 >= cnt) return;
    const int n0 = blockIdx.y * 64;

    extern __shared__ char sm[];
    const uint32_t sb = smem_u32(sm);
    const int tid = threadIdx.x, lane = tid & 31, wid = tid >> 5;
    const int g = lane >> 2, t4 = lane & 3;
    const int wm = wid >> 1, wn = wid & 1;

    // cp.async geometry: crow 0..63, cc 0..3 (16B chunk within 64B row)
    const int crow = tid >> 2, cc = tid & 3;
    const __nv_bfloat16 *axh[2], *axl[2];
    uint32_t amask = 0;
#pragma unroll
    for (int j = 0; j < 2; j++) {
        int gm = m0 + crow + 64 * j;
        int ok = gm < cnt;
        int tok = ok ? g_row_token[e * CAP + gm] : 0;
        axh[j] = g_xh + (size_t)tok * H_DIM + cc * 8;
        axl[j] = g_xl + (size_t)tok * H_DIM + cc * 8;
        amask |= (ok ? 1u : 0u) << j;
    }
    const size_t brow_off = ((size_t)e * 2 * I_DIM + n0 + crow) * H_DIM + cc * 8;
    const __nv_bfloat16* bgh = g_w1h + brow_off;
    const __nv_bfloat16* bgl = g_w1l + brow_off;
    const __nv_bfloat16* buh = g_w1h + brow_off + (size_t)I_DIM * H_DIM;
    const __nv_bfloat16* bul = g_w1l + brow_off + (size_t)I_DIM * H_DIM;
    const uint32_t dst0 = (uint32_t)(crow * SROW + cc * 16);

    // ldmatrix per-lane offsets
    const uint32_t aoff = (uint32_t)((wm * 32 + (lane & 15)) * SROW + (lane >> 4) * 16);
    const uint32_t boff = (uint32_t)((wn * 32 + (lane & 7) + ((lane >> 4) << 3)) * SROW
                                     + ((lane >> 3) & 1) * 16);

    float accg[2][4][4], accu[2][4][4];
#pragma unroll
    for (int mt = 0; mt < 2; mt++)
#pragma unroll
        for (int nt = 0; nt < 4; nt++)
#pragma unroll
            for (int i = 0; i < 4; i++) { accg[mt][nt][i] = 0.f; accu[mt][nt][i] = 0.f; }

    const int NC = H_DIM / 32;   // 64

#define G1_ISSUE(c) do { \
    uint32_t _b = sb + (uint32_t)(((c) % 3) * G1_STG); \
    int _ko = (c) * 32; \
    _Pragma("unroll") \
    for (int _j = 0; _j < 2; _j++) { \
        int _sz = ((amask >> _j) & 1) ? 16 : 0; \
        CP16(_b + dst0 + (uint32_t)(_j * 64 * SROW), axh[_j] + _ko, _sz); \
        CP16(_b + 10240 + dst0 + (uint32_t)(_j * 64 * SROW), axl[_j] + _ko, _sz); \
    } \
    CP16(_b + 20480 + dst0, bgh + _ko, 16); \
    CP16(_b + 25600 + dst0, bgl + _ko, 16); \
    CP16(_b + 30720 + dst0, buh + _ko, 16); \
    CP16(_b + 35840 + dst0, bul + _ko, 16); \
} while (0)

    G1_ISSUE(0); CP_COMMIT();
    G1_ISSUE(1); CP_COMMIT();

    for (int c = 0; c < NC; c++) {
        if (c + 2 < NC) { G1_ISSUE(c + 2); }
        CP_COMMIT();
        CP_WAIT2();
        __syncthreads();
        const uint32_t base = sb + (uint32_t)((c % 3) * G1_STG);
#pragma unroll
        for (int ks = 0; ks < 2; ks++) {
            const uint32_t ko = ks * 32;
            uint32_t ah[2][4], al_[2][4];
#pragma unroll
            for (int mt = 0; mt < 2; mt++) {
                ldsm_x4(ah[mt],  base + aoff + mt * (16 * SROW) + ko);
                ldsm_x4(al_[mt], base + 10240 + aoff + mt * (16 * SROW) + ko);
            }
            uint32_t gh[2][4], gl[2][4], uh[2][4], ul[2][4];
#pragma unroll
            for (int p = 0; p < 2; p++) {
                ldsm_x4(gh[p], base + 20480 + boff + p * (16 * SROW) + ko);
                ldsm_x4(gl[p], base + 25600 + boff + p * (16 * SROW) + ko);
                ldsm_x4(uh[p], base + 30720 + boff + p * (16 * SROW) + ko);
                ldsm_x4(ul[p], base + 35840 + boff + p * (16 * SROW) + ko);
            }
#pragma unroll
            for (int mt = 0; mt < 2; mt++)
#pragma unroll
                for (int nt = 0; nt < 4; nt++) {
                    const int p = nt >> 1, h = (nt & 1) * 2;
                    mma3(accg[mt][nt], ah[mt], al_[mt], &gh[p][h], &gl[p][h]);
                    mma3(accu[mt][nt], ah[mt], al_[mt], &uh[p][h], &ul[p][h]);
                }
        }
        __syncthreads();
    }

    // epilogue: act = silu(gate) * up, stored as bf16 hi/lo
    const int melim = cnt - m0;
#pragma unroll
    for (int mt = 0; mt < 2; mt++) {
#pragma unroll
        for (int half = 0; half < 2; half++) {
            int r = wm * 32 + mt * 16 + g + half * 8;
            if (r < melim) {
                size_t rb = (size_t)(e * CAP + m0 + r) * I_DIM + n0 + wn * 32 + 2 * t4;
#pragma unroll
                for (int nt = 0; nt < 4; nt++) {
                    float g0 = accg[mt][nt][half * 2 + 0], g1 = accg[mt][nt][half * 2 + 1];
                    float u0 = accu[mt][nt][half * 2 + 0], u1 = accu[mt][nt][half * 2 + 1];
                    float2 o;
                    o.x = u0 * (g0 / (1.f + expf(-g0)));
                    o.y = u1 * (g1 / (1.f + expf(-g1)));
                    uint32_t h, l;
                    cvt2(o, h, l);
                    *(uint32_t*)(g_acth + rb + nt * 8) = h;
                    *(uint32_t*)(g_actl + rb + nt * 8) = l;
                }
            }
        }
    }
}

// ================= GEMM2: M=128 x N=128, BK=32, deterministic atomic combine ==========
// Stage layout: Ah 0, Al 10240, Bh 20480, Bl 30720.
#define G2_STG  40960
#define G2_SMEM (3 * G2_STG)

__global__ void __launch_bounds__(256, 1) k_gemm2(float* __restrict__ out) {
    const int e = blockIdx.z;
    const int cnt = g_cnt[e];
    const int m0 = blockIdx.x * 128;
    if (m0 >= cnt) return;
    const int n0 = blockIdx.y * 128;

    extern __shared__ char sm[];
    const uint32_t sb = smem_u32(sm);
    const int tid = threadIdx.x, lane = tid & 31, wid = tid >> 5;
    const int g = lane >> 2, t4 = lane & 3;
    const int wm = wid >> 2, wn = wid & 3;

    const int crow = tid >> 2, cc = tid & 3;
    uint32_t amask = 0;
#pragma unroll
    for (int j = 0; j < 2; j++)
        if (m0 + crow + 64 * j < cnt) amask |= 1u << j;
    const size_t arow_off = (size_t)(e * CAP + m0 + crow) * I_DIM + cc * 8;
    const __nv_bfloat16* ah_b = g_acth + arow_off;
    const __nv_bfloat16* al_b = g_actl + arow_off;
    const size_t brow_off = ((size_t)e * H_DIM + n0 + crow) * I_DIM + cc * 8;
    const __nv_bfloat16* bh_b = g_w2h + brow_off;
    const __nv_bfloat16* bl_b = g_w2l + brow_off;
    const uint32_t dst0 = (uint32_t)(crow * SROW + cc * 16);

    const uint32_t aoff = (uint32_t)((wm * 64 + (lane & 15)) * SROW + (lane >> 4) * 16);
    const uint32_t boff = (uint32_t)((wn * 32 + (lane & 7) + ((lane >> 4) << 3)) * SROW
                                     + ((lane >> 3) & 1) * 16);

    float acc[4][4][4];
#pragma unroll
    for (int mt = 0; mt < 4; mt++)
#pragma unroll
        for (int nt = 0; nt < 4; nt++)
#pragma unroll
            for (int i = 0; i < 4; i++) acc[mt][nt][i] = 0.f;

    const int NC = I_DIM / 32;   // 44

#define G2_ISSUE(c) do { \
    uint32_t _b = sb + (uint32_t)(((c) % 3) * G2_STG); \
    int _ko = (c) * 32; \
    _Pragma("unroll") \
    for (int _j = 0; _j < 2; _j++) { \
        int _sz = ((amask >> _j) & 1) ? 16 : 0; \
        size_t _ro = (size_t)(_j * 64); \
        CP16(_b + dst0 + (uint32_t)(_j * 64 * SROW), ah_b + _ro * I_DIM + _ko, _sz); \
        CP16(_b + 10240 + dst0 + (uint32_t)(_j * 64 * SROW), al_b + _ro * I_DIM + _ko, _sz); \
        CP16(_b + 20480 + dst0 + (uint32_t)(_j * 64 * SROW), bh_b + _ro * I_DIM + _ko, 16); \
        CP16(_b + 30720 + dst0 + (uint32_t)(_j * 64 * SROW), bl_b + _ro * I_DIM + _ko, 16); \
    } \
} while (0)

    G2_ISSUE(0); CP_COMMIT();
    G2_ISSUE(1); CP_COMMIT();

    for (int c = 0; c < NC; c++) {
        if (c + 2 < NC) { G2_ISSUE(c + 2); }
        CP_COMMIT();
        CP_WAIT2();
        __syncthreads();
        const uint32_t base = sb + (uint32_t)((c % 3) * G2_STG);
#pragma unroll
        for (int ks = 0; ks < 2; ks++) {
            const uint32_t ko = ks * 32;
            uint32_t ahr[4][4], alr[4][4];
#pragma unroll
            for (int mt = 0; mt < 4; mt++) {
                ldsm_x4(ahr[mt], base + aoff + mt * (16 * SROW) + ko);
                ldsm_x4(alr[mt], base + 10240 + aoff + mt * (16 * SROW) + ko);
            }
            uint32_t bhr[2][4], blr[2][4];
#pragma unroll
            for (int p = 0; p < 2; p++) {
                ldsm_x4(bhr[p], base + 20480 + boff + p * (16 * SROW) + ko);
                ldsm_x4(blr[p], base + 30720 + boff + p * (16 * SROW) + ko);
            }
#pragma unroll
            for (int mt = 0; mt < 4; mt++)
#pragma unroll
                for (int nt = 0; nt < 4; nt++) {
                    const int p = nt >> 1, h = (nt & 1) * 2;
                    mma3(acc[mt][nt], ahr[mt], alr[mt], &bhr[p][h], &blr[p][h]);
                }
        }
        __syncthreads();
    }

    // epilogue: out[tok] += w * acc (2 commutative adds per element -> deterministic)
    const int melim = cnt - m0;
#pragma unroll
    for (int mt = 0; mt < 4; mt++) {
#pragma unroll
        for (int half = 0; half < 2; half++) {
            int r = wm * 64 + mt * 16 + g + half * 8;
            if (r < melim) {
                int slot = e * CAP + m0 + r;
                int tok = g_row_token[slot];
                float w = g_row_w[slot];
                float* orow = out + (size_t)tok * H_DIM + n0 + wn * 32 + 2 * t4;
#pragma unroll
                for (int nt = 0; nt < 4; nt++) {
                    atomicAdd(orow + nt * 8 + 0, w * acc[mt][nt][half * 2 + 0]);
                    atomicAdd(orow + nt * 8 + 1, w * acc[mt][nt][half * 2 + 1]);
                }
            }
        }
    }
}

// ---------------- launch ----------------
extern "C" void kernel_launch(void* const* d_in, const int* in_sizes, int n_in,
                              void* d_out, int out_size) {
    const float* x  = (const float*)d_in[0];
    const float* gw = (const float*)d_in[1];
    const float* w1 = (const float*)d_in[2];
    const float* w2 = (const float*)d_in[3];
    float* out = (float*)d_out;

    static void *p_xh = nullptr, *p_xl, *p_w1h, *p_w1l, *p_w2h, *p_w2l;
    if (!p_xh) {
        cudaGetSymbolAddress(&p_xh, g_xh);  cudaGetSymbolAddress(&p_xl, g_xl);
        cudaGetSymbolAddress(&p_w1h, g_w1h); cudaGetSymbolAddress(&p_w1l, g_w1l);
        cudaGetSymbolAddress(&p_w2h, g_w2h); cudaGetSymbolAddress(&p_w2l, g_w2l);
        cudaFuncSetAttribute(k_gemm1, cudaFuncAttributeMaxDynamicSharedMemorySize, G1_SMEM);
        cudaFuncSetAttribute(k_gemm2, cudaFuncAttributeMaxDynamicSharedMemorySize, G2_SMEM);
    }

    k_zero_counts<<<1, 32>>>();
    k_gating<<<T_TOK, 256>>>(x, gw);
    k_route<<<(T_TOK + 255) / 256, 256>>>();
    k_zero_out<<<(T_TOK * H_DIM / 4) / 256, 256>>>(out);

    const int nx = T_TOK * H_DIM / 4;
    const int n1 = E_NUM * 2 * I_DIM * H_DIM / 4;
    const int n2 = E_NUM * H_DIM * I_DIM / 4;
    k_cvt<<<nx / 256, 256>>>((const float4*)x,  (uint2*)p_xh,  (uint2*)p_xl,  nx);
    k_cvt<<<n1 / 256, 256>>>((const float4*)w1, (uint2*)p_w1h, (uint2*)p_w1l, n1);
    k_cvt<<<n2 / 256, 256>>>((const float4*)w2, (uint2*)p_w2h, (uint2*)p_w2l, n2);

    dim3 g1(CAP / 128, I_DIM / 64, E_NUM);    // (16, 22, 8)
    k_gemm1<<<g1, 256, G1_SMEM>>>();

    dim3 g2(CAP / 128, H_DIM / 128, E_NUM);   // (16, 16, 8)
    k_gemm2<<<g2, 256, G2_SMEM>>>(out);
}

// round 10
// speedup vs baseline: 1.9842x; 1.0456x over previous
#include <cuda_runtime.h>
#include <cuda_bf16.h>
#include <math.h>
#include <stdint.h>

#define T_TOK 2048
#define H_DIM 2048
#define I_DIM 1408
#define E_NUM 8
#define CAP   2048
#define NSLOT (E_NUM * CAP)
#define SROW  80           // smem row stride in bytes (32 bf16 = 64B data + 16B pad)

// ---------------- scratch ----------------
__device__ int   g_cnt[E_NUM];
__device__ int   g_sel[T_TOK][2];
__device__ float g_wts[T_TOK][2];
__device__ int   g_row_token[NSLOT];
__device__ float g_row_w[NSLOT];
// bf16 hi/lo shadows
__device__ __nv_bfloat16 g_xh[(size_t)T_TOK * H_DIM];
__device__ __nv_bfloat16 g_xl[(size_t)T_TOK * H_DIM];
__device__ __nv_bfloat16 g_w1h[(size_t)E_NUM * 2 * I_DIM * H_DIM];
__device__ __nv_bfloat16 g_w1l[(size_t)E_NUM * 2 * I_DIM * H_DIM];
__device__ __nv_bfloat16 g_w2h[(size_t)E_NUM * H_DIM * I_DIM];
__device__ __nv_bfloat16 g_w2l[(size_t)E_NUM * H_DIM * I_DIM];
__device__ __nv_bfloat16 g_acth[(size_t)NSLOT * I_DIM];
__device__ __nv_bfloat16 g_actl[(size_t)NSLOT * I_DIM];

// ---------------- helpers ----------------
__device__ __forceinline__ uint32_t smem_u32(const void* p) {
    uint32_t a;
    asm("{ .reg .u64 t; cvta.to.shared.u64 t, %1; cvt.u32.u64 %0, t; }" : "=r"(a) : "l"(p));
    return a;
}
#define CP16(dst, src, sz) \
    asm volatile("cp.async.cg.shared.global [%0], [%1], 16, %2;" :: "r"(dst), "l"(src), "r"(sz) : "memory")
#define CP_COMMIT() asm volatile("cp.async.commit_group;" ::: "memory")
#define CP_WAIT(n)  asm volatile("cp.async.wait_group %0;" :: "n"(n) : "memory")

__device__ __forceinline__ void ldsm_x4(uint32_t* r, uint32_t addr) {
    asm volatile("ldmatrix.sync.aligned.m8n8.x4.shared.b16 {%0,%1,%2,%3}, [%4];"
        : "=r"(r[0]), "=r"(r[1]), "=r"(r[2]), "=r"(r[3]) : "r"(addr));
}
__device__ __forceinline__ void cvt2(float2 v, uint32_t& h, uint32_t& l) {
    __nv_bfloat162 hb = __float22bfloat162_rn(v);
    float2 hf = __bfloat1622float2(hb);
    __nv_bfloat162 lb = __float22bfloat162_rn(make_float2(v.x - hf.x, v.y - hf.y));
    h = *(uint32_t*)&hb;
    l = *(uint32_t*)&lb;
}
__device__ __forceinline__ void mma16816(float* c, const uint32_t* a, const uint32_t* b) {
    asm volatile(
        "mma.sync.aligned.m16n8k16.row.col.f32.bf16.bf16.f32 "
        "{%0,%1,%2,%3}, {%4,%5,%6,%7}, {%8,%9}, {%0,%1,%2,%3};"
        : "+f"(c[0]), "+f"(c[1]), "+f"(c[2]), "+f"(c[3])
        : "r"(a[0]), "r"(a[1]), "r"(a[2]), "r"(a[3]), "r"(b[0]), "r"(b[1]));
}
__device__ __forceinline__ void mma3(float* c, const uint32_t* ah, const uint32_t* al,
                                     const uint32_t* bh, const uint32_t* bl) {
    mma16816(c, ah, bh);
    mma16816(c, ah, bl);
    mma16816(c, al, bh);
}

// ---------------- conversion: fp32 -> bf16 hi/lo ----------------
__global__ void k_cvt(const float4* __restrict__ src, uint2* __restrict__ hi,
                      uint2* __restrict__ lo, int n4) {
    int i = blockIdx.x * blockDim.x + threadIdx.x;
    if (i >= n4) return;
    float4 v = src[i];
    uint32_t h0, l0, h1, l1;
    cvt2(make_float2(v.x, v.y), h0, l0);
    cvt2(make_float2(v.z, v.w), h1, l1);
    hi[i] = make_uint2(h0, h1);
    lo[i] = make_uint2(l0, l1);
}

// ---------------- gating / routing (proven) ----------------
__global__ void k_zero_counts() { if (threadIdx.x < E_NUM) g_cnt[threadIdx.x] = 0; }

__global__ void k_gating(const float* __restrict__ x, const float* __restrict__ gw) {
    int t = blockIdx.x;
    const float* xr = x + (size_t)t * H_DIM;
    float acc[E_NUM];
#pragma unroll
    for (int e = 0; e < E_NUM; e++) acc[e] = 0.f;
    for (int h = threadIdx.x; h < H_DIM; h += blockDim.x) {
        float xv = xr[h];
#pragma unroll
        for (int e = 0; e < E_NUM; e++) acc[e] += xv * gw[e * H_DIM + h];
    }
#pragma unroll
    for (int e = 0; e < E_NUM; e++)
#pragma unroll
        for (int o = 16; o > 0; o >>= 1) acc[e] += __shfl_down_sync(0xffffffffu, acc[e], o);
    __shared__ float part[8][E_NUM];
    int wid = threadIdx.x >> 5, lane = threadIdx.x & 31;
    if (lane == 0)
#pragma unroll
        for (int e = 0; e < E_NUM; e++) part[wid][e] = acc[e];
    __syncthreads();
    if (threadIdx.x == 0) {
        float logit[E_NUM];
#pragma unroll
        for (int e = 0; e < E_NUM; e++) {
            float s = 0.f;
#pragma unroll
            for (int w = 0; w < 8; w++) s += part[w][e];
            logit[e] = s;
        }
        int e0 = 0;
#pragma unroll
        for (int e = 1; e < E_NUM; e++) if (logit[e] > logit[e0]) e0 = e;
        int e1 = (e0 == 0) ? 1 : 0;
#pragma unroll
        for (int e = 0; e < E_NUM; e++) if (e != e0 && logit[e] > logit[e1]) e1 = e;
        float w0 = 1.f / (1.f + expf(logit[e1] - logit[e0]));
        g_sel[t][0] = e0; g_sel[t][1] = e1;
        g_wts[t][0] = w0; g_wts[t][1] = 1.f - w0;
    }
}

__global__ void k_route() {
    int t = blockIdx.x * blockDim.x + threadIdx.x;
    if (t >= T_TOK) return;
#pragma unroll
    for (int k = 0; k < 2; k++) {
        int e = g_sel[t][k];
        int pos = atomicAdd(&g_cnt[e], 1);
        g_row_token[e * CAP + pos] = t;
        g_row_w[e * CAP + pos] = g_wts[t][k];
    }
}

__global__ void k_zero_out(float* __restrict__ out) {
    int i = blockIdx.x * blockDim.x + threadIdx.x;
    ((float4*)out)[i] = make_float4(0.f, 0.f, 0.f, 0.f);
}

// ================= GEMM1: M=128 (gathered) x N=64(gate)+64(up), BK=32 =================
// 4-stage pipeline, ONE __syncthreads per chunk.
// Stage layout (bytes): Ah 0, Al 10240, Bgh 20480, Bgl 25600, Buh 30720, Bul 35840.
#define G1_STG  40960
#define G1_SMEM (4 * G1_STG)

__global__ void __launch_bounds__(256, 1) k_gemm1() {
    const int e = blockIdx.z;
    const int cnt = g_cnt[e];
    const int m0 = blockIdx.x * 128;
    if (m0 >= cnt) return;
    const int n0 = blockIdx.y * 64;

    extern __shared__ char sm[];
    const uint32_t sb = smem_u32(sm);
    const int tid = threadIdx.x, lane = tid & 31, wid = tid >> 5;
    const int g = lane >> 2, t4 = lane & 3;
    const int wm = wid >> 1, wn = wid & 1;

    const int crow = tid >> 2, cc = tid & 3;
    const __nv_bfloat16 *axh[2], *axl[2];
    uint32_t amask = 0;
#pragma unroll
    for (int j = 0; j < 2; j++) {
        int gm = m0 + crow + 64 * j;
        int ok = gm < cnt;
        int tok = ok ? g_row_token[e * CAP + gm] : 0;
        axh[j] = g_xh + (size_t)tok * H_DIM + cc * 8;
        axl[j] = g_xl + (size_t)tok * H_DIM + cc * 8;
        amask |= (ok ? 1u : 0u) << j;
    }
    const size_t brow_off = ((size_t)e * 2 * I_DIM + n0 + crow) * H_DIM + cc * 8;
    const __nv_bfloat16* bgh = g_w1h + brow_off;
    const __nv_bfloat16* bgl = g_w1l + brow_off;
    const __nv_bfloat16* buh = g_w1h + brow_off + (size_t)I_DIM * H_DIM;
    const __nv_bfloat16* bul = g_w1l + brow_off + (size_t)I_DIM * H_DIM;
    const uint32_t dst0 = (uint32_t)(crow * SROW + cc * 16);

    const uint32_t aoff = (uint32_t)((wm * 32 + (lane & 15)) * SROW + (lane >> 4) * 16);
    const uint32_t boff = (uint32_t)((wn * 32 + (lane & 7) + ((lane >> 4) << 3)) * SROW
                                     + ((lane >> 3) & 1) * 16);

    float accg[2][4][4], accu[2][4][4];
#pragma unroll
    for (int mt = 0; mt < 2; mt++)
#pragma unroll
        for (int nt = 0; nt < 4; nt++)
#pragma unroll
            for (int i = 0; i < 4; i++) { accg[mt][nt][i] = 0.f; accu[mt][nt][i] = 0.f; }

    const int NC = H_DIM / 32;   // 64

#define G1_ISSUE(c) do { \
    uint32_t _b = sb + (uint32_t)(((c) & 3) * G1_STG); \
    int _ko = (c) * 32; \
    _Pragma("unroll") \
    for (int _j = 0; _j < 2; _j++) { \
        int _sz = ((amask >> _j) & 1) ? 16 : 0; \
        CP16(_b + dst0 + (uint32_t)(_j * 64 * SROW), axh[_j] + _ko, _sz); \
        CP16(_b + 10240 + dst0 + (uint32_t)(_j * 64 * SROW), axl[_j] + _ko, _sz); \
    } \
    CP16(_b + 20480 + dst0, bgh + _ko, 16); \
    CP16(_b + 25600 + dst0, bgl + _ko, 16); \
    CP16(_b + 30720 + dst0, buh + _ko, 16); \
    CP16(_b + 35840 + dst0, bul + _ko, 16); \
} while (0)

    G1_ISSUE(0); CP_COMMIT();
    G1_ISSUE(1); CP_COMMIT();
    G1_ISSUE(2); CP_COMMIT();

    for (int c = 0; c < NC; c++) {
        CP_WAIT(2);            // stage c landed
        __syncthreads();       // all warps see it; all are past compute(c-1)
        if (c + 3 < NC) { G1_ISSUE(c + 3); }   // overwrites stage of chunk c-1: safe
        CP_COMMIT();
        const uint32_t base = sb + (uint32_t)((c & 3) * G1_STG);
#pragma unroll
        for (int ks = 0; ks < 2; ks++) {
            const uint32_t ko = ks * 32;
            uint32_t ah[2][4], al_[2][4];
#pragma unroll
            for (int mt = 0; mt < 2; mt++) {
                ldsm_x4(ah[mt],  base + aoff + mt * (16 * SROW) + ko);
                ldsm_x4(al_[mt], base + 10240 + aoff + mt * (16 * SROW) + ko);
            }
            uint32_t gh[2][4], gl[2][4], uh[2][4], ul[2][4];
#pragma unroll
            for (int p = 0; p < 2; p++) {
                ldsm_x4(gh[p], base + 20480 + boff + p * (16 * SROW) + ko);
                ldsm_x4(gl[p], base + 25600 + boff + p * (16 * SROW) + ko);
                ldsm_x4(uh[p], base + 30720 + boff + p * (16 * SROW) + ko);
                ldsm_x4(ul[p], base + 35840 + boff + p * (16 * SROW) + ko);
            }
#pragma unroll
            for (int mt = 0; mt < 2; mt++)
#pragma unroll
                for (int nt = 0; nt < 4; nt++) {
                    const int p = nt >> 1, h = (nt & 1) * 2;
                    mma3(accg[mt][nt], ah[mt], al_[mt], &gh[p][h], &gl[p][h]);
                    mma3(accu[mt][nt], ah[mt], al_[mt], &uh[p][h], &ul[p][h]);
                }
        }
    }

    // epilogue: act = silu(gate) * up, stored as bf16 hi/lo
    const int melim = cnt - m0;
#pragma unroll
    for (int mt = 0; mt < 2; mt++) {
#pragma unroll
        for (int half = 0; half < 2; half++) {
            int r = wm * 32 + mt * 16 + g + half * 8;
            if (r < melim) {
                size_t rb = (size_t)(e * CAP + m0 + r) * I_DIM + n0 + wn * 32 + 2 * t4;
#pragma unroll
                for (int nt = 0; nt < 4; nt++) {
                    float g0 = accg[mt][nt][half * 2 + 0], g1 = accg[mt][nt][half * 2 + 1];
                    float u0 = accu[mt][nt][half * 2 + 0], u1 = accu[mt][nt][half * 2 + 1];
                    float2 o;
                    o.x = u0 * (g0 / (1.f + expf(-g0)));
                    o.y = u1 * (g1 / (1.f + expf(-g1)));
                    uint32_t h, l;
                    cvt2(o, h, l);
                    *(uint32_t*)(g_acth + rb + nt * 8) = h;
                    *(uint32_t*)(g_actl + rb + nt * 8) = l;
                }
            }
        }
    }
}

// ================= GEMM2: M=128 x N=128, BK=32, deterministic atomic combine ==========
// 4-stage pipeline, one sync per chunk. Stage: Ah 0, Al 10240, Bh 20480, Bl 30720.
#define G2_STG  40960
#define G2_SMEM (4 * G2_STG)

__global__ void __launch_bounds__(256, 1) k_gemm2(float* __restrict__ out) {
    const int e = blockIdx.z;
    const int cnt = g_cnt[e];
    const int m0 = blockIdx.x * 128;
    if (m0 >= cnt) return;
    const int n0 = blockIdx.y * 128;

    extern __shared__ char sm[];
    const uint32_t sb = smem_u32(sm);
    const int tid = threadIdx.x, lane = tid & 31, wid = tid >> 5;
    const int g = lane >> 2, t4 = lane & 3;
    const int wm = wid >> 2, wn = wid & 3;

    const int crow = tid >> 2, cc = tid & 3;
    uint32_t amask = 0;
#pragma unroll
    for (int j = 0; j < 2; j++)
        if (m0 + crow + 64 * j < cnt) amask |= 1u << j;
    const size_t arow_off = (size_t)(e * CAP + m0 + crow) * I_DIM + cc * 8;
    const __nv_bfloat16* ah_b = g_acth + arow_off;
    const __nv_bfloat16* al_b = g_actl + arow_off;
    const size_t brow_off = ((size_t)e * H_DIM + n0 + crow) * I_DIM + cc * 8;
    const __nv_bfloat16* bh_b = g_w2h + brow_off;
    const __nv_bfloat16* bl_b = g_w2l + brow_off;
    const uint32_t dst0 = (uint32_t)(crow * SROW + cc * 16);

    const uint32_t aoff = (uint32_t)((wm * 64 + (lane & 15)) * SROW + (lane >> 4) * 16);
    const uint32_t boff = (uint32_t)((wn * 32 + (lane & 7) + ((lane >> 4) << 3)) * SROW
                                     + ((lane >> 3) & 1) * 16);

    float acc[4][4][4];
#pragma unroll
    for (int mt = 0; mt < 4; mt++)
#pragma unroll
        for (int nt = 0; nt < 4; nt++)
#pragma unroll
            for (int i = 0; i < 4; i++) acc[mt][nt][i] = 0.f;

    const int NC = I_DIM / 32;   // 44

#define G2_ISSUE(c) do { \
    uint32_t _b = sb + (uint32_t)(((c) & 3) * G2_STG); \
    int _ko = (c) * 32; \
    _Pragma("unroll") \
    for (int _j = 0; _j < 2; _j++) { \
        int _sz = ((amask >> _j) & 1) ? 16 : 0; \
        size_t _ro = (size_t)(_j * 64); \
        CP16(_b + dst0 + (uint32_t)(_j * 64 * SROW), ah_b + _ro * I_DIM + _ko, _sz); \
        CP16(_b + 10240 + dst0 + (uint32_t)(_j * 64 * SROW), al_b + _ro * I_DIM + _ko, _sz); \
        CP16(_b + 20480 + dst0 + (uint32_t)(_j * 64 * SROW), bh_b + _ro * I_DIM + _ko, 16); \
        CP16(_b + 30720 + dst0 + (uint32_t)(_j * 64 * SROW), bl_b + _ro * I_DIM + _ko, 16); \
    } \
} while (0)

    G2_ISSUE(0); CP_COMMIT();
    G2_ISSUE(1); CP_COMMIT();
    G2_ISSUE(2); CP_COMMIT();

    for (int c = 0; c < NC; c++) {
        CP_WAIT(2);
        __syncthreads();
        if (c + 3 < NC) { G2_ISSUE(c + 3); }
        CP_COMMIT();
        const uint32_t base = sb + (uint32_t)((c & 3) * G2_STG);
#pragma unroll
        for (int ks = 0; ks < 2; ks++) {
            const uint32_t ko = ks * 32;
            uint32_t ahr[4][4], alr[4][4];
#pragma unroll
            for (int mt = 0; mt < 4; mt++) {
                ldsm_x4(ahr[mt], base + aoff + mt * (16 * SROW) + ko);
                ldsm_x4(alr[mt], base + 10240 + aoff + mt * (16 * SROW) + ko);
            }
            uint32_t bhr[2][4], blr[2][4];
#pragma unroll
            for (int p = 0; p < 2; p++) {
                ldsm_x4(bhr[p], base + 20480 + boff + p * (16 * SROW) + ko);
                ldsm_x4(blr[p], base + 30720 + boff + p * (16 * SROW) + ko);
            }
#pragma unroll
            for (int mt = 0; mt < 4; mt++)
#pragma unroll
                for (int nt = 0; nt < 4; nt++) {
                    const int p = nt >> 1, h = (nt & 1) * 2;
                    mma3(acc[mt][nt], ahr[mt], alr[mt], &bhr[p][h], &blr[p][h]);
                }
        }
    }

    // epilogue: out[tok] += w * acc (2 commutative adds per element -> deterministic)
    const int melim = cnt - m0;
#pragma unroll
    for (int mt = 0; mt < 4; mt++) {
#pragma unroll
        for (int half = 0; half < 2; half++) {
            int r = wm * 64 + mt * 16 + g + half * 8;
            if (r < melim) {
                int slot = e * CAP + m0 + r;
                int tok = g_row_token[slot];
                float w = g_row_w[slot];
                float* orow = out + (size_t)tok * H_DIM + n0 + wn * 32 + 2 * t4;
#pragma unroll
                for (int nt = 0; nt < 4; nt++) {
                    atomicAdd(orow + nt * 8 + 0, w * acc[mt][nt][half * 2 + 0]);
                    atomicAdd(orow + nt * 8 + 1, w * acc[mt][nt][half * 2 + 1]);
                }
            }
        }
    }
}

// ---------------- launch ----------------
extern "C" void kernel_launch(void* const* d_in, const int* in_sizes, int n_in,
                              void* d_out, int out_size) {
    const float* x  = (const float*)d_in[0];
    const float* gw = (const float*)d_in[1];
    const float* w1 = (const float*)d_in[2];
    const float* w2 = (const float*)d_in[3];
    float* out = (float*)d_out;

    static void *p_xh = nullptr, *p_xl, *p_w1h, *p_w1l, *p_w2h, *p_w2l;
    if (!p_xh) {
        cudaGetSymbolAddress(&p_xh, g_xh);  cudaGetSymbolAddress(&p_xl, g_xl);
        cudaGetSymbolAddress(&p_w1h, g_w1h); cudaGetSymbolAddress(&p_w1l, g_w1l);
        cudaGetSymbolAddress(&p_w2h, g_w2h); cudaGetSymbolAddress(&p_w2l, g_w2l);
        cudaFuncSetAttribute(k_gemm1, cudaFuncAttributeMaxDynamicSharedMemorySize, G1_SMEM);
        cudaFuncSetAttribute(k_gemm2, cudaFuncAttributeMaxDynamicSharedMemorySize, G2_SMEM);
    }

    const int nx = T_TOK * H_DIM / 4;
    const int n1 = E_NUM * 2 * I_DIM * H_DIM / 4;
    const int n2 = E_NUM * H_DIM * I_DIM / 4;

    // Launch order arranged so ncu (-s 5 -c 1) captures k_gemm1 as launch #6.
    k_zero_counts<<<1, 32>>>();                                               // 1
    k_gating<<<T_TOK, 256>>>(x, gw);                                          // 2
    k_route<<<(T_TOK + 255) / 256, 256>>>();                                  // 3
    k_cvt<<<nx / 256, 256>>>((const float4*)x,  (uint2*)p_xh,  (uint2*)p_xl,  nx);  // 4
    k_cvt<<<n1 / 256, 256>>>((const float4*)w1, (uint2*)p_w1h, (uint2*)p_w1l, n1);  // 5

    dim3 g1(CAP / 128, I_DIM / 64, E_NUM);    // (16, 22, 8)
    k_gemm1<<<g1, 256, G1_SMEM>>>();                                          // 6

    k_cvt<<<n2 / 256, 256>>>((const float4*)w2, (uint2*)p_w2h, (uint2*)p_w2l, n2);  // 7
    k_zero_out<<<(T_TOK * H_DIM / 4) / 256, 256>>>(out);                      // 8

    dim3 g2(CAP / 128, H_DIM / 128, E_NUM);   // (16, 16, 8)
    k_gemm2<<<g2, 256, G2_SMEM>>>(out);                                       // 9
}

// round 11
// speedup vs baseline: 2.5489x; 1.2846x over previous
#include <cuda_runtime.h>
#include <cuda_fp16.h>
#include <math.h>
#include <stdint.h>

#define T_TOK 2048
#define H_DIM 2048
#define I_DIM 1408
#define E_NUM 8
#define CAP   2048
#define NSLOT (E_NUM * CAP)
#define SROW  80           // smem row stride in bytes (32 fp16 = 64B data + 16B pad)

// ---------------- scratch ----------------
__device__ int   g_cnt[E_NUM];
__device__ int   g_sel[T_TOK][2];
__device__ float g_wts[T_TOK][2];
__device__ int   g_row_token[NSLOT];
__device__ float g_row_w[NSLOT];
// fp16 shadows: x hi-only; weights hi+lo; act hi-only
__device__ __half g_xh[(size_t)T_TOK * H_DIM];
__device__ __half g_w1h[(size_t)E_NUM * 2 * I_DIM * H_DIM];
__device__ __half g_w1l[(size_t)E_NUM * 2 * I_DIM * H_DIM];
__device__ __half g_w2h[(size_t)E_NUM * H_DIM * I_DIM];
__device__ __half g_w2l[(size_t)E_NUM * H_DIM * I_DIM];
__device__ __half g_acth[(size_t)NSLOT * I_DIM];

// ---------------- helpers ----------------
__device__ __forceinline__ uint32_t smem_u32(const void* p) {
    uint32_t a;
    asm("{ .reg .u64 t; cvta.to.shared.u64 t, %1; cvt.u32.u64 %0, t; }" : "=r"(a) : "l"(p));
    return a;
}
#define CP16(dst, src, sz) \
    asm volatile("cp.async.cg.shared.global [%0], [%1], 16, %2;" :: "r"(dst), "l"(src), "r"(sz) : "memory")
#define CP_COMMIT() asm volatile("cp.async.commit_group;" ::: "memory")
#define CP_WAIT(n)  asm volatile("cp.async.wait_group %0;" :: "n"(n) : "memory")

__device__ __forceinline__ void ldsm_x4(uint32_t* r, uint32_t addr) {
    asm volatile("ldmatrix.sync.aligned.m8n8.x4.shared.b16 {%0,%1,%2,%3}, [%4];"
        : "=r"(r[0]), "=r"(r[1]), "=r"(r[2]), "=r"(r[3]) : "r"(addr));
}
__device__ __forceinline__ void mma_f16(float* c, const uint32_t* a, const uint32_t* b) {
    asm volatile(
        "mma.sync.aligned.m16n8k16.row.col.f32.f16.f16.f32 "
        "{%0,%1,%2,%3}, {%4,%5,%6,%7}, {%8,%9}, {%0,%1,%2,%3};"
        : "+f"(c[0]), "+f"(c[1]), "+f"(c[2]), "+f"(c[3])
        : "r"(a[0]), "r"(a[1]), "r"(a[2]), "r"(a[3]), "r"(b[0]), "r"(b[1]));
}
// 2-MMA emulation: A_hi * (B_hi + B_lo)
__device__ __forceinline__ void mma2(float* c, const uint32_t* ah,
                                     const uint32_t* bh, const uint32_t* bl) {
    mma_f16(c, ah, bh);
    mma_f16(c, ah, bl);
}

// ---------------- conversion kernels ----------------
__global__ void k_cvt_hl(const float4* __restrict__ src, uint2* __restrict__ hi,
                         uint2* __restrict__ lo, int n4) {
    int i = blockIdx.x * blockDim.x + threadIdx.x;
    if (i >= n4) return;
    float4 v = src[i];
    __half2 h01 = __floats2half2_rn(v.x, v.y);
    __half2 h23 = __floats2half2_rn(v.z, v.w);
    float2 f01 = __half22float2(h01), f23 = __half22float2(h23);
    __half2 l01 = __floats2half2_rn(v.x - f01.x, v.y - f01.y);
    __half2 l23 = __floats2half2_rn(v.z - f23.x, v.w - f23.y);
    hi[i] = make_uint2(*(uint32_t*)&h01, *(uint32_t*)&h23);
    lo[i] = make_uint2(*(uint32_t*)&l01, *(uint32_t*)&l23);
}
__global__ void k_cvt_h(const float4* __restrict__ src, uint2* __restrict__ hi, int n4) {
    int i = blockIdx.x * blockDim.x + threadIdx.x;
    if (i >= n4) return;
    float4 v = src[i];
    __half2 h01 = __floats2half2_rn(v.x, v.y);
    __half2 h23 = __floats2half2_rn(v.z, v.w);
    hi[i] = make_uint2(*(uint32_t*)&h01, *(uint32_t*)&h23);
}

// ---------------- gating / routing (proven, exact fp32) ----------------
__global__ void k_zero_counts() { if (threadIdx.x < E_NUM) g_cnt[threadIdx.x] = 0; }

__global__ void k_gating(const float* __restrict__ x, const float* __restrict__ gw) {
    int t = blockIdx.x;
    const float* xr = x + (size_t)t * H_DIM;
    float acc[E_NUM];
#pragma unroll
    for (int e = 0; e < E_NUM; e++) acc[e] = 0.f;
    for (int h = threadIdx.x; h < H_DIM; h += blockDim.x) {
        float xv = xr[h];
#pragma unroll
        for (int e = 0; e < E_NUM; e++) acc[e] += xv * gw[e * H_DIM + h];
    }
#pragma unroll
    for (int e = 0; e < E_NUM; e++)
#pragma unroll
        for (int o = 16; o > 0; o >>= 1) acc[e] += __shfl_down_sync(0xffffffffu, acc[e], o);
    __shared__ float part[8][E_NUM];
    int wid = threadIdx.x >> 5, lane = threadIdx.x & 31;
    if (lane == 0)
#pragma unroll
        for (int e = 0; e < E_NUM; e++) part[wid][e] = acc[e];
    __syncthreads();
    if (threadIdx.x == 0) {
        float logit[E_NUM];
#pragma unroll
        for (int e = 0; e < E_NUM; e++) {
            float s = 0.f;
#pragma unroll
            for (int w = 0; w < 8; w++) s += part[w][e];
            logit[e] = s;
        }
        int e0 = 0;
#pragma unroll
        for (int e = 1; e < E_NUM; e++) if (logit[e] > logit[e0]) e0 = e;
        int e1 = (e0 == 0) ? 1 : 0;
#pragma unroll
        for (int e = 0; e < E_NUM; e++) if (e != e0 && logit[e] > logit[e1]) e1 = e;
        float w0 = 1.f / (1.f + expf(logit[e1] - logit[e0]));
        g_sel[t][0] = e0; g_sel[t][1] = e1;
        g_wts[t][0] = w0; g_wts[t][1] = 1.f - w0;
    }
}

__global__ void k_route() {
    int t = blockIdx.x * blockDim.x + threadIdx.x;
    if (t >= T_TOK) return;
#pragma unroll
    for (int k = 0; k < 2; k++) {
        int e = g_sel[t][k];
        int pos = atomicAdd(&g_cnt[e], 1);
        g_row_token[e * CAP + pos] = t;
        g_row_w[e * CAP + pos] = g_wts[t][k];
    }
}

__global__ void k_zero_out(float* __restrict__ out) {
    int i = blockIdx.x * blockDim.x + threadIdx.x;
    ((float4*)out)[i] = make_float4(0.f, 0.f, 0.f, 0.f);
}

// ================= GEMM1: M=128 (gathered) x N=64(gate)+64(up), BK=32 =================
// 5-stage pipeline, one __syncthreads per chunk.
// Stage (bytes): Ah 0 (10240), Bgh 10240, Bgl 15360, Buh 20480, Bul 25600. STG 30720.
#define G1_STG  30720
#define G1_SMEM (5 * G1_STG)

__global__ void __launch_bounds__(256, 1) k_gemm1() {
    const int e = blockIdx.z;
    const int cnt = g_cnt[e];
    const int m0 = blockIdx.x * 128;
    if (m0 >= cnt) return;
    const int n0 = blockIdx.y * 64;

    extern __shared__ char sm[];
    const uint32_t sb = smem_u32(sm);
    const int tid = threadIdx.x, lane = tid & 31, wid = tid >> 5;
    const int g = lane >> 2, t4 = lane & 3;
    const int wm = wid >> 1, wn = wid & 1;

    const int crow = tid >> 2, cc = tid & 3;
    const __half* axh[2];
    uint32_t amask = 0;
#pragma unroll
    for (int j = 0; j < 2; j++) {
        int gm = m0 + crow + 64 * j;
        int ok = gm < cnt;
        int tok = ok ? g_row_token[e * CAP + gm] : 0;
        axh[j] = g_xh + (size_t)tok * H_DIM + cc * 8;
        amask |= (ok ? 1u : 0u) << j;
    }
    const size_t brow_off = ((size_t)e * 2 * I_DIM + n0 + crow) * H_DIM + cc * 8;
    const __half* bgh = g_w1h + brow_off;
    const __half* bgl = g_w1l + brow_off;
    const __half* buh = g_w1h + brow_off + (size_t)I_DIM * H_DIM;
    const __half* bul = g_w1l + brow_off + (size_t)I_DIM * H_DIM;
    const uint32_t dst0 = (uint32_t)(crow * SROW + cc * 16);

    const uint32_t aoff = (uint32_t)((wm * 32 + (lane & 15)) * SROW + (lane >> 4) * 16);
    const uint32_t boff = (uint32_t)((wn * 32 + (lane & 7) + ((lane >> 4) << 3)) * SROW
                                     + ((lane >> 3) & 1) * 16);

    float accg[2][4][4], accu[2][4][4];
#pragma unroll
    for (int mt = 0; mt < 2; mt++)
#pragma unroll
        for (int nt = 0; nt < 4; nt++)
#pragma unroll
            for (int i = 0; i < 4; i++) { accg[mt][nt][i] = 0.f; accu[mt][nt][i] = 0.f; }

    const int NC = H_DIM / 32;   // 64

#define G1_ISSUE(c) do { \
    uint32_t _b = sb + (uint32_t)(((c) % 5) * G1_STG); \
    int _ko = (c) * 32; \
    _Pragma("unroll") \
    for (int _j = 0; _j < 2; _j++) { \
        int _sz = ((amask >> _j) & 1) ? 16 : 0; \
        CP16(_b + dst0 + (uint32_t)(_j * 64 * SROW), axh[_j] + _ko, _sz); \
    } \
    CP16(_b + 10240 + dst0, bgh + _ko, 16); \
    CP16(_b + 15360 + dst0, bgl + _ko, 16); \
    CP16(_b + 20480 + dst0, buh + _ko, 16); \
    CP16(_b + 25600 + dst0, bul + _ko, 16); \
} while (0)

    G1_ISSUE(0); CP_COMMIT();
    G1_ISSUE(1); CP_COMMIT();
    G1_ISSUE(2); CP_COMMIT();
    G1_ISSUE(3); CP_COMMIT();

    for (int c = 0; c < NC; c++) {
        CP_WAIT(3);            // stage c landed
        __syncthreads();       // all warps past compute(c-1)
        if (c + 4 < NC) { G1_ISSUE(c + 4); }   // overwrites stage of chunk c-1: safe
        CP_COMMIT();
        const uint32_t base = sb + (uint32_t)((c % 5) * G1_STG);
#pragma unroll
        for (int ks = 0; ks < 2; ks++) {
            const uint32_t ko = ks * 32;
            uint32_t ah[2][4];
#pragma unroll
            for (int mt = 0; mt < 2; mt++)
                ldsm_x4(ah[mt], base + aoff + mt * (16 * SROW) + ko);
            uint32_t gh[2][4], gl[2][4], uh[2][4], ul[2][4];
#pragma unroll
            for (int p = 0; p < 2; p++) {
                ldsm_x4(gh[p], base + 10240 + boff + p * (16 * SROW) + ko);
                ldsm_x4(gl[p], base + 15360 + boff + p * (16 * SROW) + ko);
                ldsm_x4(uh[p], base + 20480 + boff + p * (16 * SROW) + ko);
                ldsm_x4(ul[p], base + 25600 + boff + p * (16 * SROW) + ko);
            }
#pragma unroll
            for (int mt = 0; mt < 2; mt++)
#pragma unroll
                for (int nt = 0; nt < 4; nt++) {
                    const int p = nt >> 1, h = (nt & 1) * 2;
                    mma2(accg[mt][nt], ah[mt], &gh[p][h], &gl[p][h]);
                    mma2(accu[mt][nt], ah[mt], &uh[p][h], &ul[p][h]);
                }
        }
    }

    // epilogue: act = silu(gate) * up, stored fp16 (this rounding IS gemm2's A-split)
    const int melim = cnt - m0;
#pragma unroll
    for (int mt = 0; mt < 2; mt++) {
#pragma unroll
        for (int half = 0; half < 2; half++) {
            int r = wm * 32 + mt * 16 + g + half * 8;
            if (r < melim) {
                size_t rb = (size_t)(e * CAP + m0 + r) * I_DIM + n0 + wn * 32 + 2 * t4;
#pragma unroll
                for (int nt = 0; nt < 4; nt++) {
                    float g0 = accg[mt][nt][half * 2 + 0], g1 = accg[mt][nt][half * 2 + 1];
                    float u0 = accu[mt][nt][half * 2 + 0], u1 = accu[mt][nt][half * 2 + 1];
                    float o0 = u0 * (g0 / (1.f + expf(-g0)));
                    float o1 = u1 * (g1 / (1.f + expf(-g1)));
                    __half2 oh = __floats2half2_rn(o0, o1);
                    *(uint32_t*)(g_acth + rb + nt * 8) = *(uint32_t*)&oh;
                }
            }
        }
    }
}

// ================= GEMM2: M=128 x N=128, BK=32, deterministic atomic combine ==========
// 5-stage pipeline. Stage: Ah 0 (10240), Bh 10240, Bl 20480. STG 30720.
#define G2_STG  30720
#define G2_SMEM (5 * G2_STG)

__global__ void __launch_bounds__(256, 1) k_gemm2(float* __restrict__ out) {
    const int e = blockIdx.z;
    const int cnt = g_cnt[e];
    const int m0 = blockIdx.x * 128;
    if (m0 >= cnt) return;
    const int n0 = blockIdx.y * 128;

    extern __shared__ char sm[];
    const uint32_t sb = smem_u32(sm);
    const int tid = threadIdx.x, lane = tid & 31, wid = tid >> 5;
    const int g = lane >> 2, t4 = lane & 3;
    const int wm = wid >> 2, wn = wid & 3;

    const int crow = tid >> 2, cc = tid & 3;
    uint32_t amask = 0;
#pragma unroll
    for (int j = 0; j < 2; j++)
        if (m0 + crow + 64 * j < cnt) amask |= 1u << j;
    const __half* ah_b = g_acth + (size_t)(e * CAP + m0 + crow) * I_DIM + cc * 8;
    const size_t brow_off = ((size_t)e * H_DIM + n0 + crow) * I_DIM + cc * 8;
    const __half* bh_b = g_w2h + brow_off;
    const __half* bl_b = g_w2l + brow_off;
    const uint32_t dst0 = (uint32_t)(crow * SROW + cc * 16);

    const uint32_t aoff = (uint32_t)((wm * 64 + (lane & 15)) * SROW + (lane >> 4) * 16);
    const uint32_t boff = (uint32_t)((wn * 32 + (lane & 7) + ((lane >> 4) << 3)) * SROW
                                     + ((lane >> 3) & 1) * 16);

    float acc[4][4][4];
#pragma unroll
    for (int mt = 0; mt < 4; mt++)
#pragma unroll
        for (int nt = 0; nt < 4; nt++)
#pragma unroll
            for (int i = 0; i < 4; i++) acc[mt][nt][i] = 0.f;

    const int NC = I_DIM / 32;   // 44

#define G2_ISSUE(c) do { \
    uint32_t _b = sb + (uint32_t)(((c) % 5) * G2_STG); \
    int _ko = (c) * 32; \
    _Pragma("unroll") \
    for (int _j = 0; _j < 2; _j++) { \
        int _sz = ((amask >> _j) & 1) ? 16 : 0; \
        size_t _ro = (size_t)(_j * 64); \
        CP16(_b + dst0 + (uint32_t)(_j * 64 * SROW), ah_b + _ro * I_DIM + _ko, _sz); \
        CP16(_b + 10240 + dst0 + (uint32_t)(_j * 64 * SROW), bh_b + _ro * I_DIM + _ko, 16); \
        CP16(_b + 20480 + dst0 + (uint32_t)(_j * 64 * SROW), bl_b + _ro * I_DIM + _ko, 16); \
    } \
} while (0)

    G2_ISSUE(0); CP_COMMIT();
    G2_ISSUE(1); CP_COMMIT();
    G2_ISSUE(2); CP_COMMIT();
    G2_ISSUE(3); CP_COMMIT();

    for (int c = 0; c < NC; c++) {
        CP_WAIT(3);
        __syncthreads();
        if (c + 4 < NC) { G2_ISSUE(c + 4); }
        CP_COMMIT();
        const uint32_t base = sb + (uint32_t)((c % 5) * G2_STG);
#pragma unroll
        for (int ks = 0; ks < 2; ks++) {
            const uint32_t ko = ks * 32;
            uint32_t ahr[4][4];
#pragma unroll
            for (int mt = 0; mt < 4; mt++)
                ldsm_x4(ahr[mt], base + aoff + mt * (16 * SROW) + ko);
            uint32_t bhr[2][4], blr[2][4];
#pragma unroll
            for (int p = 0; p < 2; p++) {
                ldsm_x4(bhr[p], base + 10240 + boff + p * (16 * SROW) + ko);
                ldsm_x4(blr[p], base + 20480 + boff + p * (16 * SROW) + ko);
            }
#pragma unroll
            for (int mt = 0; mt < 4; mt++)
#pragma unroll
                for (int nt = 0; nt < 4; nt++) {
                    const int p = nt >> 1, h = (nt & 1) * 2;
                    mma2(acc[mt][nt], ahr[mt], &bhr[p][h], &blr[p][h]);
                }
        }
    }

    // epilogue: out[tok] += w * acc (2 commutative adds per element -> deterministic)
    const int melim = cnt - m0;
#pragma unroll
    for (int mt = 0; mt < 4; mt++) {
#pragma unroll
        for (int half = 0; half < 2; half++) {
            int r = wm * 64 + mt * 16 + g + half * 8;
            if (r < melim) {
                int slot = e * CAP + m0 + r;
                int tok = g_row_token[slot];
                float w = g_row_w[slot];
                float* orow = out + (size_t)tok * H_DIM + n0 + wn * 32 + 2 * t4;
#pragma unroll
                for (int nt = 0; nt < 4; nt++) {
                    atomicAdd(orow + nt * 8 + 0, w * acc[mt][nt][half * 2 + 0]);
                    atomicAdd(orow + nt * 8 + 1, w * acc[mt][nt][half * 2 + 1]);
                }
            }
        }
    }
}

// ---------------- launch ----------------
extern "C" void kernel_launch(void* const* d_in, const int* in_sizes, int n_in,
                              void* d_out, int out_size) {
    const float* x  = (const float*)d_in[0];
    const float* gw = (const float*)d_in[1];
    const float* w1 = (const float*)d_in[2];
    const float* w2 = (const float*)d_in[3];
    float* out = (float*)d_out;

    static void *p_xh = nullptr, *p_w1h, *p_w1l, *p_w2h, *p_w2l;
    if (!p_xh) {
        cudaGetSymbolAddress(&p_xh, g_xh);
        cudaGetSymbolAddress(&p_w1h, g_w1h); cudaGetSymbolAddress(&p_w1l, g_w1l);
        cudaGetSymbolAddress(&p_w2h, g_w2h); cudaGetSymbolAddress(&p_w2l, g_w2l);
        cudaFuncSetAttribute(k_gemm1, cudaFuncAttributeMaxDynamicSharedMemorySize, G1_SMEM);
        cudaFuncSetAttribute(k_gemm2, cudaFuncAttributeMaxDynamicSharedMemorySize, G2_SMEM);
    }

    const int nx = T_TOK * H_DIM / 4;
    const int n1 = E_NUM * 2 * I_DIM * H_DIM / 4;
    const int n2 = E_NUM * H_DIM * I_DIM / 4;

    k_zero_counts<<<1, 32>>>();
    k_gating<<<T_TOK, 256>>>(x, gw);
    k_route<<<(T_TOK + 255) / 256, 256>>>();
    k_cvt_h<<<nx / 256, 256>>>((const float4*)x, (uint2*)p_xh, nx);
    k_cvt_hl<<<n1 / 256, 256>>>((const float4*)w1, (uint2*)p_w1h, (uint2*)p_w1l, n1);

    dim3 g1(CAP / 128, I_DIM / 64, E_NUM);    // (16, 22, 8), early exit on cnt
    k_gemm1<<<g1, 256, G1_SMEM>>>();

    k_cvt_hl<<<n2 / 256, 256>>>((const float4*)w2, (uint2*)p_w2h, (uint2*)p_w2l, n2);
    k_zero_out<<<(T_TOK * H_DIM / 4) / 256, 256>>>(out);

    dim3 g2(CAP / 128, H_DIM / 128, E_NUM);   // (16, 16, 8)
    k_gemm2<<<g2, 256, G2_SMEM>>>(out);
}

// round 12
// speedup vs baseline: 4.3130x; 1.6921x over previous
#include <cuda_runtime.h>
#include <cuda_fp16.h>
#include <math.h>
#include <stdint.h>

#define T_TOK 2048
#define H_DIM 2048
#define I_DIM 1408
#define E_NUM 8
#define CAP   2048
#define NSLOT (E_NUM * CAP)
#define SROW  80           // smem row stride in bytes (32 fp16 = 64B data + 16B pad)

// ---------------- scratch ----------------
__device__ int   g_cnt[E_NUM];
__device__ int   g_sel[T_TOK][2];
__device__ float g_wts[T_TOK][2];
__device__ int   g_row_token[NSLOT];
__device__ float g_row_w[NSLOT];
// fp16 shadows (hi only — pure fp16 GEMMs, error budget 5.8e-4 per calibration)
__device__ __half g_xh[(size_t)T_TOK * H_DIM];
__device__ __half g_w1h[(size_t)E_NUM * 2 * I_DIM * H_DIM];
__device__ __half g_w2h[(size_t)E_NUM * H_DIM * I_DIM];
__device__ __half g_acth[(size_t)NSLOT * I_DIM];

// ---------------- helpers ----------------
__device__ __forceinline__ uint32_t smem_u32(const void* p) {
    uint32_t a;
    asm("{ .reg .u64 t; cvta.to.shared.u64 t, %1; cvt.u32.u64 %0, t; }" : "=r"(a) : "l"(p));
    return a;
}
#define CP16(dst, src, sz) \
    asm volatile("cp.async.cg.shared.global [%0], [%1], 16, %2;" :: "r"(dst), "l"(src), "r"(sz) : "memory")
#define CP_COMMIT() asm volatile("cp.async.commit_group;" ::: "memory")
#define CP_WAIT(n)  asm volatile("cp.async.wait_group %0;" :: "n"(n) : "memory")

__device__ __forceinline__ void ldsm_x4(uint32_t* r, uint32_t addr) {
    asm volatile("ldmatrix.sync.aligned.m8n8.x4.shared.b16 {%0,%1,%2,%3}, [%4];"
        : "=r"(r[0]), "=r"(r[1]), "=r"(r[2]), "=r"(r[3]) : "r"(addr));
}
__device__ __forceinline__ void mma_f16(float* c, const uint32_t* a, const uint32_t* b) {
    asm volatile(
        "mma.sync.aligned.m16n8k16.row.col.f32.f16.f16.f32 "
        "{%0,%1,%2,%3}, {%4,%5,%6,%7}, {%8,%9}, {%0,%1,%2,%3};"
        : "+f"(c[0]), "+f"(c[1]), "+f"(c[2]), "+f"(c[3])
        : "r"(a[0]), "r"(a[1]), "r"(a[2]), "r"(a[3]), "r"(b[0]), "r"(b[1]));
}

// ---------------- conversion: fp32 -> fp16, 4-way MLP grid-stride ----------------
__global__ void k_cvt_h4(const float4* __restrict__ src, uint2* __restrict__ hi, int n4) {
    int i0 = (blockIdx.x * blockDim.x + threadIdx.x) * 4;
    if (i0 + 3 >= n4) {
        for (int i = i0; i < n4; i++) {
            float4 v = src[i];
            __half2 h01 = __floats2half2_rn(v.x, v.y);
            __half2 h23 = __floats2half2_rn(v.z, v.w);
            hi[i] = make_uint2(*(uint32_t*)&h01, *(uint32_t*)&h23);
        }
        return;
    }
    float4 v[4];
#pragma unroll
    for (int j = 0; j < 4; j++) v[j] = src[i0 + j];
#pragma unroll
    for (int j = 0; j < 4; j++) {
        __half2 h01 = __floats2half2_rn(v[j].x, v[j].y);
        __half2 h23 = __floats2half2_rn(v[j].z, v[j].w);
        hi[i0 + j] = make_uint2(*(uint32_t*)&h01, *(uint32_t*)&h23);
    }
}

// ---------------- gating / routing (proven, exact fp32) ----------------
__global__ void k_zero_counts() { if (threadIdx.x < E_NUM) g_cnt[threadIdx.x] = 0; }

__global__ void k_gating(const float* __restrict__ x, const float* __restrict__ gw) {
    int t = blockIdx.x;
    const float* xr = x + (size_t)t * H_DIM;
    float acc[E_NUM];
#pragma unroll
    for (int e = 0; e < E_NUM; e++) acc[e] = 0.f;
    for (int h = threadIdx.x; h < H_DIM; h += blockDim.x) {
        float xv = xr[h];
#pragma unroll
        for (int e = 0; e < E_NUM; e++) acc[e] += xv * gw[e * H_DIM + h];
    }
#pragma unroll
    for (int e = 0; e < E_NUM; e++)
#pragma unroll
        for (int o = 16; o > 0; o >>= 1) acc[e] += __shfl_down_sync(0xffffffffu, acc[e], o);
    __shared__ float part[8][E_NUM];
    int wid = threadIdx.x >> 5, lane = threadIdx.x & 31;
    if (lane == 0)
#pragma unroll
        for (int e = 0; e < E_NUM; e++) part[wid][e] = acc[e];
    __syncthreads();
    if (threadIdx.x == 0) {
        float logit[E_NUM];
#pragma unroll
        for (int e = 0; e < E_NUM; e++) {
            float s = 0.f;
#pragma unroll
            for (int w = 0; w < 8; w++) s += part[w][e];
            logit[e] = s;
        }
        int e0 = 0;
#pragma unroll
        for (int e = 1; e < E_NUM; e++) if (logit[e] > logit[e0]) e0 = e;
        int e1 = (e0 == 0) ? 1 : 0;
#pragma unroll
        for (int e = 0; e < E_NUM; e++) if (e != e0 && logit[e] > logit[e1]) e1 = e;
        float w0 = 1.f / (1.f + expf(logit[e1] - logit[e0]));
        g_sel[t][0] = e0; g_sel[t][1] = e1;
        g_wts[t][0] = w0; g_wts[t][1] = 1.f - w0;
    }
}

__global__ void k_route() {
    int t = blockIdx.x * blockDim.x + threadIdx.x;
    if (t >= T_TOK) return;
#pragma unroll
    for (int k = 0; k < 2; k++) {
        int e = g_sel[t][k];
        int pos = atomicAdd(&g_cnt[e], 1);
        g_row_token[e * CAP + pos] = t;
        g_row_w[e * CAP + pos] = g_wts[t][k];
    }
}

__global__ void k_zero_out(float* __restrict__ out) {
    int i = blockIdx.x * blockDim.x + threadIdx.x;
    ((float4*)out)[i] = make_float4(0.f, 0.f, 0.f, 0.f);
}

// ================= GEMM1: M=128 (gathered) x N=64(gate)+64(up), BK=32 =================
// Pure fp16 single MMA. 5-stage pipeline, one __syncthreads per chunk.
// Stage (bytes): Ah 0 (10240), Bgh 10240 (5120), Buh 15360 (5120). STG 20480.
#define G1_STG  20480
#define G1_SMEM (5 * G1_STG)

__global__ void __launch_bounds__(256) k_gemm1() {
    const int e = blockIdx.z;
    const int cnt = g_cnt[e];
    const int m0 = blockIdx.x * 128;
    if (m0 >= cnt) return;
    const int n0 = blockIdx.y * 64;

    extern __shared__ char sm[];
    const uint32_t sb = smem_u32(sm);
    const int tid = threadIdx.x, lane = tid & 31, wid = tid >> 5;
    const int g = lane >> 2, t4 = lane & 3;
    const int wm = wid >> 1, wn = wid & 1;

    const int crow = tid >> 2, cc = tid & 3;
    const __half* axh[2];
    uint32_t amask = 0;
#pragma unroll
    for (int j = 0; j < 2; j++) {
        int gm = m0 + crow + 64 * j;
        int ok = gm < cnt;
        int tok = ok ? g_row_token[e * CAP + gm] : 0;
        axh[j] = g_xh + (size_t)tok * H_DIM + cc * 8;
        amask |= (ok ? 1u : 0u) << j;
    }
    const size_t brow_off = ((size_t)e * 2 * I_DIM + n0 + crow) * H_DIM + cc * 8;
    const __half* bgh = g_w1h + brow_off;
    const __half* buh = g_w1h + brow_off + (size_t)I_DIM * H_DIM;
    const uint32_t dst0 = (uint32_t)(crow * SROW + cc * 16);

    const uint32_t aoff = (uint32_t)((wm * 32 + (lane & 15)) * SROW + (lane >> 4) * 16);
    const uint32_t boff = (uint32_t)((wn * 32 + (lane & 7) + ((lane >> 4) << 3)) * SROW
                                     + ((lane >> 3) & 1) * 16);

    float accg[2][4][4], accu[2][4][4];
#pragma unroll
    for (int mt = 0; mt < 2; mt++)
#pragma unroll
        for (int nt = 0; nt < 4; nt++)
#pragma unroll
            for (int i = 0; i < 4; i++) { accg[mt][nt][i] = 0.f; accu[mt][nt][i] = 0.f; }

    const int NC = H_DIM / 32;   // 64

#define G1_ISSUE(c) do { \
    uint32_t _b = sb + (uint32_t)(((c) % 5) * G1_STG); \
    int _ko = (c) * 32; \
    _Pragma("unroll") \
    for (int _j = 0; _j < 2; _j++) { \
        int _sz = ((amask >> _j) & 1) ? 16 : 0; \
        CP16(_b + dst0 + (uint32_t)(_j * 64 * SROW), axh[_j] + _ko, _sz); \
    } \
    CP16(_b + 10240 + dst0, bgh + _ko, 16); \
    CP16(_b + 15360 + dst0, buh + _ko, 16); \
} while (0)

    G1_ISSUE(0); CP_COMMIT();
    G1_ISSUE(1); CP_COMMIT();
    G1_ISSUE(2); CP_COMMIT();
    G1_ISSUE(3); CP_COMMIT();

    for (int c = 0; c < NC; c++) {
        CP_WAIT(3);            // stage c landed
        __syncthreads();       // all warps past compute(c-1)
        if (c + 4 < NC) { G1_ISSUE(c + 4); }
        CP_COMMIT();
        const uint32_t base = sb + (uint32_t)((c % 5) * G1_STG);
#pragma unroll
        for (int ks = 0; ks < 2; ks++) {
            const uint32_t ko = ks * 32;
            uint32_t ah[2][4];
#pragma unroll
            for (int mt = 0; mt < 2; mt++)
                ldsm_x4(ah[mt], base + aoff + mt * (16 * SROW) + ko);
            uint32_t gh[2][4], uh[2][4];
#pragma unroll
            for (int p = 0; p < 2; p++) {
                ldsm_x4(gh[p], base + 10240 + boff + p * (16 * SROW) + ko);
                ldsm_x4(uh[p], base + 15360 + boff + p * (16 * SROW) + ko);
            }
#pragma unroll
            for (int mt = 0; mt < 2; mt++)
#pragma unroll
                for (int nt = 0; nt < 4; nt++) {
                    const int p = nt >> 1, h = (nt & 1) * 2;
                    mma_f16(accg[mt][nt], ah[mt], &gh[p][h]);
                    mma_f16(accu[mt][nt], ah[mt], &uh[p][h]);
                }
        }
    }

    // epilogue: act = silu(gate) * up, stored fp16
    const int melim = cnt - m0;
#pragma unroll
    for (int mt = 0; mt < 2; mt++) {
#pragma unroll
        for (int half = 0; half < 2; half++) {
            int r = wm * 32 + mt * 16 + g + half * 8;
            if (r < melim) {
                size_t rb = (size_t)(e * CAP + m0 + r) * I_DIM + n0 + wn * 32 + 2 * t4;
#pragma unroll
                for (int nt = 0; nt < 4; nt++) {
                    float g0 = accg[mt][nt][half * 2 + 0], g1 = accg[mt][nt][half * 2 + 1];
                    float u0 = accu[mt][nt][half * 2 + 0], u1 = accu[mt][nt][half * 2 + 1];
                    float o0 = u0 * (g0 / (1.f + expf(-g0)));
                    float o1 = u1 * (g1 / (1.f + expf(-g1)));
                    __half2 oh = __floats2half2_rn(o0, o1);
                    *(uint32_t*)(g_acth + rb + nt * 8) = *(uint32_t*)&oh;
                }
            }
        }
    }
}

// ================= GEMM2: M=128 x N=128, BK=32, deterministic atomic combine ==========
// Pure fp16 single MMA. 5-stage pipeline. Stage: Ah 0 (10240), Bh 10240 (10240). STG 20480.
#define G2_STG  20480
#define G2_SMEM (5 * G2_STG)

__global__ void __launch_bounds__(256) k_gemm2(float* __restrict__ out) {
    const int e = blockIdx.z;
    const int cnt = g_cnt[e];
    const int m0 = blockIdx.x * 128;
    if (m0 >= cnt) return;
    const int n0 = blockIdx.y * 128;

    extern __shared__ char sm[];
    const uint32_t sb = smem_u32(sm);
    const int tid = threadIdx.x, lane = tid & 31, wid = tid >> 5;
    const int g = lane >> 2, t4 = lane & 3;
    const int wm = wid >> 2, wn = wid & 3;

    const int crow = tid >> 2, cc = tid & 3;
    uint32_t amask = 0;
#pragma unroll
    for (int j = 0; j < 2; j++)
        if (m0 + crow + 64 * j < cnt) amask |= 1u << j;
    const __half* ah_b = g_acth + (size_t)(e * CAP + m0 + crow) * I_DIM + cc * 8;
    const __half* bh_b = g_w2h + ((size_t)e * H_DIM + n0 + crow) * I_DIM + cc * 8;
    const uint32_t dst0 = (uint32_t)(crow * SROW + cc * 16);

    const uint32_t aoff = (uint32_t)((wm * 64 + (lane & 15)) * SROW + (lane >> 4) * 16);
    const uint32_t boff = (uint32_t)((wn * 32 + (lane & 7) + ((lane >> 4) << 3)) * SROW
                                     + ((lane >> 3) & 1) * 16);

    float acc[4][4][4];
#pragma unroll
    for (int mt = 0; mt < 4; mt++)
#pragma unroll
        for (int nt = 0; nt < 4; nt++)
#pragma unroll
            for (int i = 0; i < 4; i++) acc[mt][nt][i] = 0.f;

    const int NC = I_DIM / 32;   // 44

#define G2_ISSUE(c) do { \
    uint32_t _b = sb + (uint32_t)(((c) % 5) * G2_STG); \
    int _ko = (c) * 32; \
    _Pragma("unroll") \
    for (int _j = 0; _j < 2; _j++) { \
        int _sz = ((amask >> _j) & 1) ? 16 : 0; \
        size_t _ro = (size_t)(_j * 64); \
        CP16(_b + dst0 + (uint32_t)(_j * 64 * SROW), ah_b + _ro * I_DIM + _ko, _sz); \
        CP16(_b + 10240 + dst0 + (uint32_t)(_j * 64 * SROW), bh_b + _ro * I_DIM + _ko, 16); \
    } \
} while (0)

    G2_ISSUE(0); CP_COMMIT();
    G2_ISSUE(1); CP_COMMIT();
    G2_ISSUE(2); CP_COMMIT();
    G2_ISSUE(3); CP_COMMIT();

    for (int c = 0; c < NC; c++) {
        CP_WAIT(3);
        __syncthreads();
        if (c + 4 < NC) { G2_ISSUE(c + 4); }
        CP_COMMIT();
        const uint32_t base = sb + (uint32_t)((c % 5) * G2_STG);
#pragma unroll
        for (int ks = 0; ks < 2; ks++) {
            const uint32_t ko = ks * 32;
            uint32_t ahr[4][4];
#pragma unroll
            for (int mt = 0; mt < 4; mt++)
                ldsm_x4(ahr[mt], base + aoff + mt * (16 * SROW) + ko);
            uint32_t bhr[2][4];
#pragma unroll
            for (int p = 0; p < 2; p++)
                ldsm_x4(bhr[p], base + 10240 + boff + p * (16 * SROW) + ko);
#pragma unroll
            for (int mt = 0; mt < 4; mt++)
#pragma unroll
                for (int nt = 0; nt < 4; nt++) {
                    const int p = nt >> 1, h = (nt & 1) * 2;
                    mma_f16(acc[mt][nt], ahr[mt], &bhr[p][h]);
                }
        }
    }

    // epilogue: out[tok] += w * acc (2 commutative adds per element -> deterministic)
    const int melim = cnt - m0;
#pragma unroll
    for (int mt = 0; mt < 4; mt++) {
#pragma unroll
        for (int half = 0; half < 2; half++) {
            int r = wm * 64 + mt * 16 + g + half * 8;
            if (r < melim) {
                int slot = e * CAP + m0 + r;
                int tok = g_row_token[slot];
                float w = g_row_w[slot];
                float* orow = out + (size_t)tok * H_DIM + n0 + wn * 32 + 2 * t4;
#pragma unroll
                for (int nt = 0; nt < 4; nt++) {
                    atomicAdd(orow + nt * 8 + 0, w * acc[mt][nt][half * 2 + 0]);
                    atomicAdd(orow + nt * 8 + 1, w * acc[mt][nt][half * 2 + 1]);
                }
            }
        }
    }
}

// ---------------- launch ----------------
extern "C" void kernel_launch(void* const* d_in, const int* in_sizes, int n_in,
                              void* d_out, int out_size) {
    const float* x  = (const float*)d_in[0];
    const float* gw = (const float*)d_in[1];
    const float* w1 = (const float*)d_in[2];
    const float* w2 = (const float*)d_in[3];
    float* out = (float*)d_out;

    static void *p_xh = nullptr, *p_w1h, *p_w2h;
    if (!p_xh) {
        cudaGetSymbolAddress(&p_xh, g_xh);
        cudaGetSymbolAddress(&p_w1h, g_w1h);
        cudaGetSymbolAddress(&p_w2h, g_w2h);
        cudaFuncSetAttribute(k_gemm1, cudaFuncAttributeMaxDynamicSharedMemorySize, G1_SMEM);
        cudaFuncSetAttribute(k_gemm2, cudaFuncAttributeMaxDynamicSharedMemorySize, G2_SMEM);
    }

    const int nx = T_TOK * H_DIM / 4;
    const int n1 = E_NUM * 2 * I_DIM * H_DIM / 4;
    const int n2 = E_NUM * H_DIM * I_DIM / 4;

    k_zero_counts<<<1, 32>>>();
    k_gating<<<T_TOK, 256>>>(x, gw);
    k_route<<<(T_TOK + 255) / 256, 256>>>();
    k_cvt_h4<<<nx / 1024, 256>>>((const float4*)x, (uint2*)p_xh, nx);
    k_cvt_h4<<<n1 / 1024, 256>>>((const float4*)w1, (uint2*)p_w1h, n1);

    dim3 g1(CAP / 128, I_DIM / 64, E_NUM);    // (16, 22, 8), early exit on cnt
    k_gemm1<<<g1, 256, G1_SMEM>>>();

    k_cvt_h4<<<n2 / 1024, 256>>>((const float4*)w2, (uint2*)p_w2h, n2);
    k_zero_out<<<(T_TOK * H_DIM / 4) / 256, 256>>>(out);

    dim3 g2(CAP / 128, H_DIM / 128, E_NUM);   // (16, 16, 8)
    k_gemm2<<<g2, 256, G2_SMEM>>>(out);
}